// round 8
// baseline (speedup 1.0000x reference)
#include <cuda_runtime.h>
#include <cuda_bf16.h>
#include <mma.h>
#include <math.h>
#include <stdint.h>

using namespace nvcuda;

#define N_NODES 116
#define N_EDGES 1160
#define C_IN    64
#define T_IN    657
#define C_OUT   256
#define F_DIM   653
#define LDF     656                 // fp32 row stride
#define M_ROWS  (N_NODES * C_OUT)   // 29696
#define M_TILES 232                 // 29696/128
#define N_TILES 6                   // 768/128
#define NPAD    768
#define LKB     672                 // bf16 row stride (padded K, mult of 32)
#define KT_PHASE 42                 // 672/16
#define KT_TOTAL 84

#define BK      16
#define SROWB   48                  // padded smem row bytes (24 bf16) -> conflict-free LDSM
#define MAT_B   (128 * SROWB)       // 6144 bytes per matrix tile
#define STAGE_B (4 * MAT_B)         // 24576: Ah, Al, Bh, Bl
#define STAGES  4
#define GEMM_SMEM (STAGES * STAGE_B)   // 98304; epilogue reuses (128*132*4 = 67584)

// element offsets within a stage (bf16 units)
#define OFF_ALe 3072
#define OFF_BHe 6144
#define OFF_BLe 9216

// single consistent dynamic-smem declaration for ALL kernels
extern __shared__ __align__(128) unsigned char dyn_smem[];

// ---------------- device scratch --------------------------------------------
__device__ __align__(16) float g_bufA[(size_t)M_ROWS * LDF];
__device__ __align__(16) float g_bufB[(size_t)M_ROWS * LDF];
__device__ __align__(16) __nv_bfloat16 g_aggh[(size_t)M_ROWS * LKB];
__device__ __align__(16) __nv_bfloat16 g_aggl[(size_t)M_ROWS * LKB];
__device__ __align__(16) __nv_bfloat16 g_hh0[(size_t)M_ROWS * LKB];
__device__ __align__(16) __nv_bfloat16 g_hl0[(size_t)M_ROWS * LKB];
__device__ __align__(16) __nv_bfloat16 g_hh1[(size_t)M_ROWS * LKB];
__device__ __align__(16) __nv_bfloat16 g_hl1[(size_t)M_ROWS * LKB];
__device__ __align__(16) __nv_bfloat16 g_wlh[(size_t)NPAD * LKB];
__device__ __align__(16) __nv_bfloat16 g_wll[(size_t)NPAD * LKB];
__device__ __align__(16) __nv_bfloat16 g_wrh[(size_t)NPAD * LKB];
__device__ __align__(16) __nv_bfloat16 g_wrl[(size_t)NPAD * LKB];
__device__ int   g_offs[N_NODES + 1];
__device__ int   g_list[N_EDGES];
__device__ float g_mean[C_OUT * LDF];
__device__ float g_fc1 [C_OUT * 128];

// ---------------- helpers -----------------------------------------------------
__device__ __forceinline__ uint32_t smem_u32(const void* p) {
    uint32_t a;
    asm("{ .reg .u64 t; cvta.to.shared.u64 t, %1; cvt.u32.u64 %0, t; }" : "=r"(a) : "l"(p));
    return a;
}
__device__ __forceinline__ void cpa16(uint32_t dst, const void* src) {
    asm volatile("cp.async.cg.shared.global [%0], [%1], 16;" :: "r"(dst), "l"(src));
}
#define CP_COMMIT() asm volatile("cp.async.commit_group;" ::: "memory")
#define CP_WAIT2()  asm volatile("cp.async.wait_group 2;" ::: "memory")

__device__ __forceinline__ void bsplit(float v, uint16_t& h, uint16_t& l) {
    __nv_bfloat16 hb = __float2bfloat16(v);
    __nv_bfloat16 lb = __float2bfloat16(v - __bfloat162float(hb));
    h = __bfloat16_as_ushort(hb);
    l = __bfloat16_as_ushort(lb);
}
__device__ __forceinline__ uint2 pack4(uint16_t a, uint16_t b, uint16_t c, uint16_t d) {
    uint2 r;
    r.x = (uint32_t)a | ((uint32_t)b << 16);
    r.y = (uint32_t)c | ((uint32_t)d << 16);
    return r;
}

// ---------------- CSR build (edge_index arrives as int32) ---------------------
__global__ void build_csr(const int* __restrict__ ei) {
    __shared__ int cnt[N_NODES + 1];
    __shared__ int offs[N_NODES + 1];
    int tid = threadIdx.x;
    for (int i = tid; i <= N_NODES; i += blockDim.x) cnt[i] = 0;
    __syncthreads();
    for (int e = tid; e < N_EDGES; e += blockDim.x) {
        int dst = min(max(ei[N_EDGES + e], 0), N_NODES - 1);
        atomicAdd(&cnt[dst], 1);
    }
    __syncthreads();
    if (tid == 0) {
        int s = 0;
        for (int i = 0; i < N_NODES; i++) { offs[i] = s; s += cnt[i]; }
        offs[N_NODES] = s;
    }
    __syncthreads();
    for (int i = tid; i <= N_NODES; i += blockDim.x) { g_offs[i] = offs[i]; cnt[i] = offs[i]; }
    __syncthreads();
    for (int e = tid; e < N_EDGES; e += blockDim.x) {
        int src = min(max(ei[e], 0), N_NODES - 1);
        int dst = min(max(ei[N_EDGES + e], 0), N_NODES - 1);
        int pos = atomicAdd(&cnt[dst], 1);
        if (pos >= 0 && pos < N_EDGES) g_list[pos] = src;
    }
}

// ---------------- weight convert -> row-major bf16 hi/lo [768][672] -----------
__global__ void conv_weights(const float* __restrict__ wl, const float* __restrict__ wr) {
    int idx = blockIdx.x * blockDim.x + threadIdx.x;   // over 768 * 168 quads
    if (idx >= NPAD * (LKB / 4)) return;
    int nrow = idx / (LKB / 4);
    int k0   = (idx % (LKB / 4)) * 4;
    size_t off = (size_t)nrow * LKB + k0;
    uint16_t lh[4], ll[4], rh[4], rl[4];
#pragma unroll
    for (int e = 0; e < 4; e++) {
        int k = k0 + e;
        float a = (nrow < F_DIM && k < F_DIM) ? wl[(size_t)nrow * F_DIM + k] : 0.f;
        float b = (nrow < F_DIM && k < F_DIM) ? wr[(size_t)nrow * F_DIM + k] : 0.f;
        bsplit(a, lh[e], ll[e]);
        bsplit(b, rh[e], rl[e]);
    }
    *(uint2*)(g_wlh + off) = pack4(lh[0], lh[1], lh[2], lh[3]);
    *(uint2*)(g_wll + off) = pack4(ll[0], ll[1], ll[2], ll[3]);
    *(uint2*)(g_wrh + off) = pack4(rh[0], rh[1], rh[2], rh[3]);
    *(uint2*)(g_wrl + off) = pack4(rl[0], rl[1], rl[2], rl[3]);
}

// ---------------- grouped Conv1d -> bufA (fp32) + hh0/hl0 (bf16) --------------
#define XS_STRIDE 660
#define CONV_SMEM ((16 * XS_STRIDE + 64 * 80) * 4)
__global__ void conv1d_grouped(const float* __restrict__ x,
                               const float* __restrict__ w,
                               const float* __restrict__ b) {
    float* smem = (float*)dyn_smem;
    float* xs = smem;
    float* ws = smem + 16 * XS_STRIDE;
    int n = blockIdx.x, g = blockIdx.y;
    int tid = threadIdx.x;

    const float* xbase = x + ((size_t)n * C_IN + (size_t)g * 16) * T_IN;
    for (int i = tid; i < 16 * T_IN; i += blockDim.x) {
        int ic = i / T_IN, t = i % T_IN;
        xs[ic * XS_STRIDE + t] = xbase[i];
    }
    for (int i = tid; i < 64 * 80; i += blockDim.x)
        ws[i] = w[(size_t)g * 64 * 80 + i];
    __syncthreads();

    for (int task = tid; task < 64 * 164; task += blockDim.x) {
        int oc = task / 164;
        int t0 = (task % 164) * 4;
        float bias = b[g * 64 + oc];
        float a0 = bias, a1 = bias, a2 = bias, a3 = bias;
        const float* wrow = &ws[oc * 80];
#pragma unroll
        for (int i = 0; i < 16; i++) {
            float4 x0 = *(const float4*)&xs[i * XS_STRIDE + t0];
            float4 x1 = *(const float4*)&xs[i * XS_STRIDE + t0 + 4];
            float xv[8] = {x0.x, x0.y, x0.z, x0.w, x1.x, x1.y, x1.z, x1.w};
#pragma unroll
            for (int k = 0; k < 5; k++) {
                float wv = wrow[i * 5 + k];
                a0 = fmaf(xv[0 + k], wv, a0);
                a1 = fmaf(xv[1 + k], wv, a1);
                a2 = fmaf(xv[2 + k], wv, a2);
                a3 = fmaf(xv[3 + k], wv, a3);
            }
        }
        float z0 = (t0 + 0 < F_DIM) ? a0 : 0.f;
        float z1 = (t0 + 1 < F_DIM) ? a1 : 0.f;
        float z2 = (t0 + 2 < F_DIM) ? a2 : 0.f;
        float z3 = (t0 + 3 < F_DIM) ? a3 : 0.f;
        int row = n * C_OUT + g * 64 + oc;
        float* out = &g_bufA[(size_t)row * LDF + t0];
        out[0] = z0; out[1] = z1; out[2] = z2; out[3] = z3;
        uint16_t h[4], l[4];
        bsplit(z0, h[0], l[0]); bsplit(z1, h[1], l[1]);
        bsplit(z2, h[2], l[2]); bsplit(z3, h[3], l[3]);
        size_t off = (size_t)row * LKB + t0;
        *(uint2*)(g_hh0 + off) = pack4(h[0], h[1], h[2], h[3]);
        *(uint2*)(g_hl0 + off) = pack4(l[0], l[1], l[2], l[3]);
    }
    // zero the bf16 K-pad tail (cols 656..671) for this block's 64 rows
    for (int i = tid; i < 64 * 4; i += blockDim.x) {
        int oc = i / 4;
        int c0 = 656 + (i % 4) * 4;
        int row = n * C_OUT + g * 64 + oc;
        size_t off = (size_t)row * LKB + c0;
        *(uint2*)(g_hh0 + off) = make_uint2(0u, 0u);
        *(uint2*)(g_hl0 + off) = make_uint2(0u, 0u);
    }
}

// ---------------- SAGE max-aggregation -> aggh/aggl (bf16 row-major) ----------
__global__ void sage_agg(int src) {
    const float* h = src ? g_bufB : g_bufA;
    int row = blockIdx.x;          // n*256 + c
    int n = row >> 8;
    int c = row & 255;
    int beg = g_offs[n], end = g_offs[n + 1];
    size_t obase = (size_t)row * LKB;
    for (int v = threadIdx.x; v < LKB / 4; v += blockDim.x) {
        int f0 = v * 4;
        float4 m = make_float4(0.f, 0.f, 0.f, 0.f);
        if (f0 < LDF && end > beg) {
            m = make_float4(-3.4e38f, -3.4e38f, -3.4e38f, -3.4e38f);
            for (int e = beg; e < end; e++) {
                int s = g_list[e];
                float4 t = *(const float4*)(h + ((size_t)s * C_OUT + c) * LDF + f0);
                m.x = fmaxf(m.x, t.x); m.y = fmaxf(m.y, t.y);
                m.z = fmaxf(m.z, t.z); m.w = fmaxf(m.w, t.w);
            }
        }
        uint16_t hh[4], ll[4];
        bsplit(m.x, hh[0], ll[0]); bsplit(m.y, hh[1], ll[1]);
        bsplit(m.z, hh[2], ll[2]); bsplit(m.w, hh[3], ll[3]);
        *(uint2*)(g_aggh + obase + f0) = pack4(hh[0], hh[1], hh[2], hh[3]);
        *(uint2*)(g_aggl + obase + f0) = pack4(ll[0], ll[1], ll[2], ll[3]);
    }
}

// ---------------- WMMA fused SAGE GEMM ----------------------------------------
// C[128x128] = agg@Wl^T + h@Wr^T (3-term bf16 split), bias in epilogue.
// 4-stage cp.async pipeline (BK=16), ONE barrier per k-iteration.
// smem rows padded to 48B -> conflict-free ldmatrix.
__device__ __forceinline__ void stage_copy(uint32_t sbase, int tid,
                                           const __nv_bfloat16* pAh, const __nv_bfloat16* pAl,
                                           const __nv_bfloat16* pBh, const __nv_bfloat16* pBl) {
    int row = tid >> 1, half = tid & 1;            // 128 rows x 2 halves
    uint32_t so = (uint32_t)row * SROWB + half * 16;
    size_t   go = (size_t)row * LKB + half * 8;
    cpa16(sbase +             so, pAh + go);
    cpa16(sbase + MAT_B     + so, pAl + go);
    cpa16(sbase + MAT_B * 2 + so, pBh + go);
    cpa16(sbase + MAT_B * 3 + so, pBl + go);
    CP_COMMIT();
}

__global__ void __launch_bounds__(256, 2) sage_gemm(int src, int writeB,
                                                    const float* __restrict__ bias) {
    __shared__ float sbias[128];
    const int tid = threadIdx.x;
    const int wid = tid >> 5;
    const int m0 = blockIdx.x * 128;
    const int n0 = blockIdx.y * 128;

    const __nv_bfloat16* AhArr[2] = { g_aggh, src ? g_hh1 : g_hh0 };
    const __nv_bfloat16* AlArr[2] = { g_aggl, src ? g_hl1 : g_hl0 };
    const __nv_bfloat16* BhArr[2] = { g_wlh, g_wrh };
    const __nv_bfloat16* BlArr[2] = { g_wll, g_wrl };
    float*          Out  = src ? g_bufA : g_bufB;
    __nv_bfloat16*  OutH = src ? g_hh0 : g_hh1;
    __nv_bfloat16*  OutL = src ? g_hl0 : g_hl1;

    if (tid < 128) {
        int cg = n0 + tid;
        sbias[tid] = (cg < F_DIM) ? bias[cg] : 0.f;
    }

    const uint32_t smem_base = smem_u32(dyn_smem);

    // prologue: stages 0,1,2 (all phase 0 since KT_PHASE=42)
#pragma unroll
    for (int p = 0; p < 3; p++) {
        int k0 = p * BK;
        stage_copy(smem_base + p * STAGE_B, tid,
                   AhArr[0] + (size_t)m0 * LKB + k0,
                   AlArr[0] + (size_t)m0 * LKB + k0,
                   BhArr[0] + (size_t)n0 * LKB + k0,
                   BlArr[0] + (size_t)n0 * LKB + k0);
    }

    const int wm = (wid & 3) * 32;      // warp m offset within tile
    const int wn = (wid >> 2) * 64;     // warp n offset within tile

    wmma::fragment<wmma::accumulator, 16, 16, 16, float> acc[2][4];
#pragma unroll
    for (int i = 0; i < 2; i++)
#pragma unroll
        for (int j = 0; j < 4; j++) wmma::fill_fragment(acc[i][j], 0.f);

    for (int kt = 0; kt < KT_TOTAL; kt++) {
        CP_WAIT2();                 // stage kt landed (3 in flight -> wait to 2)
        __syncthreads();            // also: all warps finished compute of kt-1
        int nk = kt + 3;
        if (nk < KT_TOTAL) {        // refill buffer (nk&3) == ((kt-1)&3), safe
            int ph = (nk >= KT_PHASE) ? 1 : 0;
            int k0 = (nk - ph * KT_PHASE) * BK;
            stage_copy(smem_base + (nk & 3) * STAGE_B, tid,
                       AhArr[ph] + (size_t)m0 * LKB + k0,
                       AlArr[ph] + (size_t)m0 * LKB + k0,
                       BhArr[ph] + (size_t)n0 * LKB + k0,
                       BlArr[ph] + (size_t)n0 * LKB + k0);
        } else {
            CP_COMMIT();            // keep group counting consistent
        }
        const __nv_bfloat16* sA = (const __nv_bfloat16*)(dyn_smem + (kt & 3) * STAGE_B);
        wmma::fragment<wmma::matrix_a, 16, 16, 16, __nv_bfloat16, wmma::row_major> ah[2], al[2];
        wmma::fragment<wmma::matrix_b, 16, 16, 16, __nv_bfloat16, wmma::col_major> bh[4], bl[4];
#pragma unroll
        for (int i = 0; i < 2; i++) {
            const __nv_bfloat16* pa = sA + (wm + i * 16) * (SROWB / 2);
            wmma::load_matrix_sync(ah[i], pa, SROWB / 2);
            wmma::load_matrix_sync(al[i], pa + OFF_ALe, SROWB / 2);
        }
#pragma unroll
        for (int j = 0; j < 4; j++) {
            const __nv_bfloat16* pb = sA + OFF_BHe + (wn + j * 16) * (SROWB / 2);
            wmma::load_matrix_sync(bh[j], pb, SROWB / 2);
            wmma::load_matrix_sync(bl[j], pb + OFF_ALe, SROWB / 2);
        }
#pragma unroll
        for (int i = 0; i < 2; i++)
#pragma unroll
            for (int j = 0; j < 4; j++) {
                wmma::mma_sync(acc[i][j], ah[i], bh[j], acc[i][j]);
                wmma::mma_sync(acc[i][j], al[i], bh[j], acc[i][j]);
                wmma::mma_sync(acc[i][j], ah[i], bl[j], acc[i][j]);
            }
    }

    // epilogue: stage accumulators through smem (reuse pipeline smem)
    __syncthreads();
    float* Cs = (float*)dyn_smem;       // [128][132]
#pragma unroll
    for (int i = 0; i < 2; i++)
#pragma unroll
        for (int j = 0; j < 4; j++)
            wmma::store_matrix_sync(&Cs[(wm + i * 16) * 132 + wn + j * 16], acc[i][j],
                                    132, wmma::mem_row_major);
    __syncthreads();

#pragma unroll
    for (int t = 0; t < 16; t++) {
        int q = tid + t * 256;          // 0..4095
        int row = q >> 5;
        int col = (q & 31) * 4;
        float v0 = Cs[row * 132 + col + 0] + sbias[col + 0];
        float v1 = Cs[row * 132 + col + 1] + sbias[col + 1];
        float v2 = Cs[row * 132 + col + 2] + sbias[col + 2];
        float v3 = Cs[row * 132 + col + 3] + sbias[col + 3];
        int cg = n0 + col;
        int m = m0 + row;
        if (cg < LDF) {
            *(float4*)(Out + (size_t)m * LDF + cg) = make_float4(v0, v1, v2, v3);
        }
        if (writeB && cg < LKB) {
            uint16_t h[4], l[4];
            bsplit(v0, h[0], l[0]); bsplit(v1, h[1], l[1]);
            bsplit(v2, h[2], l[2]); bsplit(v3, h[3], l[3]);
            size_t off = (size_t)m * LKB + cg;
            *(uint2*)(OutH + off) = pack4(h[0], h[1], h[2], h[3]);
            *(uint2*)(OutL + off) = pack4(l[0], l[1], l[2], l[3]);
        }
    }
}

// ---------------- mean pool -> g_mean ------------------------------------------
__global__ void mean_pool(int src) {
    const float* h = src ? g_bufB : g_bufA;
    int idx = blockIdx.x * blockDim.x + threadIdx.x;
    if (idx >= C_OUT * LDF) return;
    int c = idx / LDF, f = idx % LDF;
    float s = 0.f;
    for (int n = 0; n < N_NODES; n++)
        s += h[((size_t)n * C_OUT + c) * LDF + f];
    g_mean[idx] = s * (1.f / N_NODES);
}

__device__ __forceinline__ float gelu_exact(float x) {
    return 0.5f * x * (1.f + erff(x * 0.70710678118654752f));
}

// ---------------- fc1 + gelu ----------------------------------------------------
__global__ void fc1_kernel(const float* __restrict__ w, const float* __restrict__ b) {
    __shared__ float row[F_DIM];
    int c = blockIdx.x;
    int tid = threadIdx.x;
    for (int f = tid; f < F_DIM; f += blockDim.x) row[f] = g_mean[c * LDF + f];
    __syncthreads();
    int warp = tid >> 5, lane = tid & 31;
    for (int g = warp; g < 128; g += blockDim.x / 32) {
        const float* wr = w + (size_t)g * F_DIM;
        float acc = 0.f;
        for (int f = lane; f < F_DIM; f += 32) acc = fmaf(row[f], wr[f], acc);
#pragma unroll
        for (int o = 16; o; o >>= 1) acc += __shfl_xor_sync(0xffffffffu, acc, o);
        if (lane == 0) g_fc1[c * 128 + g] = gelu_exact(acc + b[g]);
    }
}

// ---------------- fc2 + gelu + fc3 + softmax ------------------------------------
__global__ void head_kernel(const float* __restrict__ f2w, const float* __restrict__ f2b,
                            const float* __restrict__ f3w, const float* __restrict__ f3b,
                            float* __restrict__ out) {
    __shared__ float r1[128];
    __shared__ float r2[32];
    __shared__ float r3[4];
    int c = blockIdx.x;
    int tid = threadIdx.x;
    for (int i = tid; i < 128; i += 32) r1[i] = g_fc1[c * 128 + i];
    __syncthreads();
    {
        float acc = f2b[tid];
        const float* wr = f2w + (size_t)tid * 128;
        for (int f = 0; f < 128; f++) acc = fmaf(r1[f], wr[f], acc);
        r2[tid] = gelu_exact(acc);
    }
    __syncthreads();
    if (tid < 4) {
        float a = f3b[tid];
        const float* wr = f3w + (size_t)tid * 32;
        for (int f = 0; f < 32; f++) a = fmaf(r2[f], wr[f], a);
        r3[tid] = a;
    }
    __syncthreads();
    if (tid == 0) {
        float mx = fmaxf(fmaxf(r3[0], r3[1]), fmaxf(r3[2], r3[3]));
        float e0 = expf(r3[0] - mx), e1 = expf(r3[1] - mx);
        float e2 = expf(r3[2] - mx), e3 = expf(r3[3] - mx);
        float inv = 1.f / (e0 + e1 + e2 + e3);
        out[c * 4 + 0] = e0 * inv;
        out[c * 4 + 1] = e1 * inv;
        out[c * 4 + 2] = e2 * inv;
        out[c * 4 + 3] = e3 * inv;
    }
}

// ---------------- launch --------------------------------------------------------
extern "C" void kernel_launch(void* const* d_in, const int* in_sizes, int n_in,
                              void* d_out, int out_size) {
    const float* x      = (const float*)d_in[0];
    const int*   ei     = (const int*)d_in[1];
    const float* conv_w = (const float*)d_in[2];
    const float* conv_b = (const float*)d_in[3];
    const float* wl     = (const float*)d_in[4];
    const float* wr     = (const float*)d_in[5];
    const float* sb     = (const float*)d_in[6];
    const float* f1w    = (const float*)d_in[7];
    const float* f1b    = (const float*)d_in[8];
    const float* f2w    = (const float*)d_in[9];
    const float* f2b    = (const float*)d_in[10];
    const float* f3w    = (const float*)d_in[11];
    const float* f3b    = (const float*)d_in[12];
    float* out = (float*)d_out;

    cudaFuncSetAttribute(conv1d_grouped, cudaFuncAttributeMaxDynamicSharedMemorySize, CONV_SMEM);
    cudaFuncSetAttribute(sage_gemm,      cudaFuncAttributeMaxDynamicSharedMemorySize, GEMM_SMEM);

    build_csr<<<1, 128>>>(ei);
    conv_weights<<<(NPAD * (LKB / 4) + 255) / 256, 256>>>(wl, wr);
    conv1d_grouped<<<dim3(N_NODES, 4), 256, CONV_SMEM>>>(x, conv_w, conv_b);

    // 3 SAGE layers. l0: A->B (h: hh0 -> hh1), l1: B->A (hh1 -> hh0), l2: A->B
    for (int l = 0; l < 3; l++) {
        int src = l & 1;
        sage_agg<<<M_ROWS, 128>>>(src);
        sage_gemm<<<dim3(M_TILES, N_TILES), 256, GEMM_SMEM>>>(src, l < 2 ? 1 : 0, sb);
    }

    mean_pool<<<(C_OUT * LDF + 255) / 256, 256>>>(1);
    fc1_kernel<<<256, 128>>>(f1w, f1b);
    head_kernel<<<256, 32>>>(f2w, f2b, f3w, f3b, out);
}

// round 9
// speedup vs baseline: 1.5992x; 1.5992x over previous
#include <cuda_runtime.h>
#include <cuda_fp16.h>
#include <mma.h>
#include <math.h>
#include <stdint.h>

using namespace nvcuda;

#define N_NODES 116
#define N_EDGES 1160
#define C_IN    64
#define T_IN    657
#define C_OUT   256
#define F_DIM   653
#define LDF     656                 // fp32 row stride
#define M_ROWS  (N_NODES * C_OUT)   // 29696
#define M_TILES 232                 // 29696/128
#define N_TILES 6                   // 768/128
#define NPAD    768
#define LKB     672                 // fp16 row stride (padded K, mult of 32)
#define KT_PHASE 21                 // 672/32
#define KT_TOTAL 42

#define BK      32
#define SROW    56                  // padded smem row (fp16 elems): 112B -> conflict-free LDSM
#define MAT_B   (128 * SROW * 2)    // 14336 bytes per matrix tile
#define STAGE_B (3 * MAT_B)         // 43008: Ah, Al, Bh
#define STAGES  2
#define GEMM_SMEM (STAGES * STAGE_B)   // 86016; epilogue reuses (128*132*4 = 67584)

// element offsets within a stage (fp16 units)
#define OFF_ALe 7168
#define OFF_BHe 14336

// single consistent dynamic-smem declaration for ALL kernels
extern __shared__ __align__(128) unsigned char dyn_smem[];

// ---------------- device scratch --------------------------------------------
__device__ __align__(16) float g_bufA[(size_t)M_ROWS * LDF];
__device__ __align__(16) float g_bufB[(size_t)M_ROWS * LDF];
__device__ __align__(16) __half g_aggh[(size_t)M_ROWS * LKB];
__device__ __align__(16) __half g_aggl[(size_t)M_ROWS * LKB];
__device__ __align__(16) __half g_hh0[(size_t)M_ROWS * LKB];
__device__ __align__(16) __half g_hl0[(size_t)M_ROWS * LKB];
__device__ __align__(16) __half g_hh1[(size_t)M_ROWS * LKB];
__device__ __align__(16) __half g_hl1[(size_t)M_ROWS * LKB];
__device__ __align__(16) __half g_wlh[(size_t)NPAD * LKB];
__device__ __align__(16) __half g_wrh[(size_t)NPAD * LKB];
__device__ int   g_offs[N_NODES + 1];
__device__ int   g_list[N_EDGES];
__device__ float g_mean[C_OUT * LDF];
__device__ float g_fc1 [C_OUT * 128];

// ---------------- helpers -----------------------------------------------------
__device__ __forceinline__ uint32_t smem_u32(const void* p) {
    uint32_t a;
    asm("{ .reg .u64 t; cvta.to.shared.u64 t, %1; cvt.u32.u64 %0, t; }" : "=r"(a) : "l"(p));
    return a;
}
__device__ __forceinline__ void cpa16(uint32_t dst, const void* src) {
    asm volatile("cp.async.cg.shared.global [%0], [%1], 16;" :: "r"(dst), "l"(src));
}
#define CP_COMMIT() asm volatile("cp.async.commit_group;" ::: "memory")
#define CP_WAIT1()  asm volatile("cp.async.wait_group 1;" ::: "memory")

// fp16 split: v = hi + lo, hi = fp16(v), lo = fp16(v - hi)
__device__ __forceinline__ void fsplit(float v, uint16_t& h, uint16_t& l) {
    __half hb = __float2half_rn(v);
    __half lb = __float2half_rn(v - __half2float(hb));
    h = __half_as_ushort(hb);
    l = __half_as_ushort(lb);
}
__device__ __forceinline__ uint2 pack4(uint16_t a, uint16_t b, uint16_t c, uint16_t d) {
    uint2 r;
    r.x = (uint32_t)a | ((uint32_t)b << 16);
    r.y = (uint32_t)c | ((uint32_t)d << 16);
    return r;
}

// ---------------- CSR build (edge_index arrives as int32) ---------------------
__global__ void build_csr(const int* __restrict__ ei) {
    __shared__ int cnt[N_NODES + 1];
    __shared__ int offs[N_NODES + 1];
    int tid = threadIdx.x;
    for (int i = tid; i <= N_NODES; i += blockDim.x) cnt[i] = 0;
    __syncthreads();
    for (int e = tid; e < N_EDGES; e += blockDim.x) {
        int dst = min(max(ei[N_EDGES + e], 0), N_NODES - 1);
        atomicAdd(&cnt[dst], 1);
    }
    __syncthreads();
    if (tid == 0) {
        int s = 0;
        for (int i = 0; i < N_NODES; i++) { offs[i] = s; s += cnt[i]; }
        offs[N_NODES] = s;
    }
    __syncthreads();
    for (int i = tid; i <= N_NODES; i += blockDim.x) { g_offs[i] = offs[i]; cnt[i] = offs[i]; }
    __syncthreads();
    for (int e = tid; e < N_EDGES; e += blockDim.x) {
        int src = min(max(ei[e], 0), N_NODES - 1);
        int dst = min(max(ei[N_EDGES + e], 0), N_NODES - 1);
        int pos = atomicAdd(&cnt[dst], 1);
        if (pos >= 0 && pos < N_EDGES) g_list[pos] = src;
    }
}

// ---------------- weight convert -> row-major fp16 hi [768][672] --------------
__global__ void conv_weights(const float* __restrict__ wl, const float* __restrict__ wr) {
    int idx = blockIdx.x * blockDim.x + threadIdx.x;   // over 768 * 168 quads
    if (idx >= NPAD * (LKB / 4)) return;
    int nrow = idx / (LKB / 4);
    int k0   = (idx % (LKB / 4)) * 4;
    size_t off = (size_t)nrow * LKB + k0;
    uint16_t lh[4], rh[4];
#pragma unroll
    for (int e = 0; e < 4; e++) {
        int k = k0 + e;
        float a = (nrow < F_DIM && k < F_DIM) ? wl[(size_t)nrow * F_DIM + k] : 0.f;
        float b = (nrow < F_DIM && k < F_DIM) ? wr[(size_t)nrow * F_DIM + k] : 0.f;
        lh[e] = __half_as_ushort(__float2half_rn(a));
        rh[e] = __half_as_ushort(__float2half_rn(b));
    }
    *(uint2*)(g_wlh + off) = pack4(lh[0], lh[1], lh[2], lh[3]);
    *(uint2*)(g_wrh + off) = pack4(rh[0], rh[1], rh[2], rh[3]);
}

// ---------------- grouped Conv1d -> bufA (fp32) + hh0/hl0 (fp16) --------------
#define XS_STRIDE 660
#define CONV_SMEM ((16 * XS_STRIDE + 64 * 80) * 4)
__global__ void conv1d_grouped(const float* __restrict__ x,
                               const float* __restrict__ w,
                               const float* __restrict__ b) {
    float* smem = (float*)dyn_smem;
    float* xs = smem;
    float* ws = smem + 16 * XS_STRIDE;
    int n = blockIdx.x, g = blockIdx.y;
    int tid = threadIdx.x;

    const float* xbase = x + ((size_t)n * C_IN + (size_t)g * 16) * T_IN;
    for (int i = tid; i < 16 * T_IN; i += blockDim.x) {
        int ic = i / T_IN, t = i % T_IN;
        xs[ic * XS_STRIDE + t] = xbase[i];
    }
    for (int i = tid; i < 64 * 80; i += blockDim.x)
        ws[i] = w[(size_t)g * 64 * 80 + i];
    __syncthreads();

    for (int task = tid; task < 64 * 164; task += blockDim.x) {
        int oc = task / 164;
        int t0 = (task % 164) * 4;
        float bias = b[g * 64 + oc];
        float a0 = bias, a1 = bias, a2 = bias, a3 = bias;
        const float* wrow = &ws[oc * 80];
#pragma unroll
        for (int i = 0; i < 16; i++) {
            float4 x0 = *(const float4*)&xs[i * XS_STRIDE + t0];
            float4 x1 = *(const float4*)&xs[i * XS_STRIDE + t0 + 4];
            float xv[8] = {x0.x, x0.y, x0.z, x0.w, x1.x, x1.y, x1.z, x1.w};
#pragma unroll
            for (int k = 0; k < 5; k++) {
                float wv = wrow[i * 5 + k];
                a0 = fmaf(xv[0 + k], wv, a0);
                a1 = fmaf(xv[1 + k], wv, a1);
                a2 = fmaf(xv[2 + k], wv, a2);
                a3 = fmaf(xv[3 + k], wv, a3);
            }
        }
        float z0 = (t0 + 0 < F_DIM) ? a0 : 0.f;
        float z1 = (t0 + 1 < F_DIM) ? a1 : 0.f;
        float z2 = (t0 + 2 < F_DIM) ? a2 : 0.f;
        float z3 = (t0 + 3 < F_DIM) ? a3 : 0.f;
        int row = n * C_OUT + g * 64 + oc;
        float* out = &g_bufA[(size_t)row * LDF + t0];
        out[0] = z0; out[1] = z1; out[2] = z2; out[3] = z3;
        uint16_t h[4], l[4];
        fsplit(z0, h[0], l[0]); fsplit(z1, h[1], l[1]);
        fsplit(z2, h[2], l[2]); fsplit(z3, h[3], l[3]);
        size_t off = (size_t)row * LKB + t0;
        *(uint2*)(g_hh0 + off) = pack4(h[0], h[1], h[2], h[3]);
        *(uint2*)(g_hl0 + off) = pack4(l[0], l[1], l[2], l[3]);
    }
    // zero the fp16 K-pad tail (cols 656..671) for this block's 64 rows
    for (int i = tid; i < 64 * 4; i += blockDim.x) {
        int oc = i / 4;
        int c0 = 656 + (i % 4) * 4;
        int row = n * C_OUT + g * 64 + oc;
        size_t off = (size_t)row * LKB + c0;
        *(uint2*)(g_hh0 + off) = make_uint2(0u, 0u);
        *(uint2*)(g_hl0 + off) = make_uint2(0u, 0u);
    }
}

// ---------------- SAGE max-aggregation -> aggh/aggl (fp16 row-major) ----------
__global__ void sage_agg(int src) {
    const float* h = src ? g_bufB : g_bufA;
    int row = blockIdx.x;          // n*256 + c
    int n = row >> 8;
    int c = row & 255;
    int beg = g_offs[n], end = g_offs[n + 1];
    size_t obase = (size_t)row * LKB;
    for (int v = threadIdx.x; v < LKB / 4; v += blockDim.x) {
        int f0 = v * 4;
        float4 m = make_float4(0.f, 0.f, 0.f, 0.f);
        if (f0 < LDF && end > beg) {
            m = make_float4(-3.4e38f, -3.4e38f, -3.4e38f, -3.4e38f);
            for (int e = beg; e < end; e++) {
                int s = g_list[e];
                float4 t = *(const float4*)(h + ((size_t)s * C_OUT + c) * LDF + f0);
                m.x = fmaxf(m.x, t.x); m.y = fmaxf(m.y, t.y);
                m.z = fmaxf(m.z, t.z); m.w = fmaxf(m.w, t.w);
            }
        }
        uint16_t hh[4], ll[4];
        fsplit(m.x, hh[0], ll[0]); fsplit(m.y, hh[1], ll[1]);
        fsplit(m.z, hh[2], ll[2]); fsplit(m.w, hh[3], ll[3]);
        *(uint2*)(g_aggh + obase + f0) = pack4(hh[0], hh[1], hh[2], hh[3]);
        *(uint2*)(g_aggl + obase + f0) = pack4(ll[0], ll[1], ll[2], ll[3]);
    }
}

// ---------------- WMMA fused SAGE GEMM ----------------------------------------
// C[128x128] = agg@Wl^T + h@Wr^T; A split into fp16 hi+lo (2 terms), W fp16 hi.
// 2-stage cp.async pipeline (BK=32), smem rows padded to 112B (conflict-free LDSM).
__device__ __forceinline__ void stage_copy(uint32_t sbase, int tid,
                                           const __half* pAh, const __half* pAl,
                                           const __half* pBh) {
#pragma unroll
    for (int half_ = 0; half_ < 2; half_++) {
        int c = tid + half_ * 256;      // 0..511
        int row = c >> 2;               // 0..127
        int col = (c & 3) << 3;         // 0,8,16,24
        uint32_t so = (uint32_t)row * (SROW * 2) + col * 2;
        size_t go = (size_t)row * LKB + col;
        cpa16(sbase +             so, pAh + go);
        cpa16(sbase + MAT_B     + so, pAl + go);
        cpa16(sbase + MAT_B * 2 + so, pBh + go);
    }
    CP_COMMIT();
}

__global__ void __launch_bounds__(256, 2) sage_gemm(int src, int writeB,
                                                    const float* __restrict__ bias) {
    __shared__ float sbias[128];
    const int tid = threadIdx.x;
    const int wid = tid >> 5;
    const int m0 = blockIdx.x * 128;
    const int n0 = blockIdx.y * 128;

    const __half* AhArr[2] = { g_aggh, src ? g_hh1 : g_hh0 };
    const __half* AlArr[2] = { g_aggl, src ? g_hl1 : g_hl0 };
    const __half* BhArr[2] = { g_wlh, g_wrh };
    float*   Out  = src ? g_bufA : g_bufB;
    __half*  OutH = src ? g_hh0 : g_hh1;
    __half*  OutL = src ? g_hl0 : g_hl1;

    if (tid < 128) {
        int cg = n0 + tid;
        sbias[tid] = (cg < F_DIM) ? bias[cg] : 0.f;
    }

    const uint32_t smem_base = smem_u32(dyn_smem);

    // prologue: stages 0,1 (both phase 0 since KT_PHASE=21 > 1)
#pragma unroll
    for (int p = 0; p < 2; p++) {
        int k0 = p * BK;
        stage_copy(smem_base + p * STAGE_B, tid,
                   AhArr[0] + (size_t)m0 * LKB + k0,
                   AlArr[0] + (size_t)m0 * LKB + k0,
                   BhArr[0] + (size_t)n0 * LKB + k0);
    }

    const int wm = (wid & 3) * 32;      // warp m offset within tile
    const int wn = (wid >> 2) * 64;     // warp n offset within tile

    wmma::fragment<wmma::accumulator, 16, 16, 16, float> acc[2][4];
#pragma unroll
    for (int i = 0; i < 2; i++)
#pragma unroll
        for (int j = 0; j < 4; j++) wmma::fill_fragment(acc[i][j], 0.f);

    for (int kt = 0; kt < KT_TOTAL; kt++) {
        CP_WAIT1();
        __syncthreads();
        const __half* sA = (const __half*)(dyn_smem + (kt & 1) * STAGE_B);
        const __half* sBh = sA + OFF_BHe;
#pragma unroll
        for (int ks = 0; ks < 2; ks++) {
            wmma::fragment<wmma::matrix_a, 16, 16, 16, __half, wmma::row_major> ah[2], al[2];
            wmma::fragment<wmma::matrix_b, 16, 16, 16, __half, wmma::col_major> bh[4];
#pragma unroll
            for (int i = 0; i < 2; i++) {
                const __half* pa = sA + (wm + i * 16) * SROW + ks * 16;
                wmma::load_matrix_sync(ah[i], pa, SROW);
                wmma::load_matrix_sync(al[i], pa + OFF_ALe, SROW);
            }
#pragma unroll
            for (int j = 0; j < 4; j++) {
                const __half* pb = sBh + (wn + j * 16) * SROW + ks * 16;
                wmma::load_matrix_sync(bh[j], pb, SROW);
            }
#pragma unroll
            for (int i = 0; i < 2; i++)
#pragma unroll
                for (int j = 0; j < 4; j++) {
                    wmma::mma_sync(acc[i][j], ah[i], bh[j], acc[i][j]);
                    wmma::mma_sync(acc[i][j], al[i], bh[j], acc[i][j]);
                }
        }
        __syncthreads();           // all warps done reading stage kt&1
        int nk = kt + 2;
        if (nk < KT_TOTAL) {
            int ph = (nk >= KT_PHASE) ? 1 : 0;
            int k0 = (nk - ph * KT_PHASE) * BK;
            stage_copy(smem_base + (kt & 1) * STAGE_B, tid,
                       AhArr[ph] + (size_t)m0 * LKB + k0,
                       AlArr[ph] + (size_t)m0 * LKB + k0,
                       BhArr[ph] + (size_t)n0 * LKB + k0);
        } else {
            CP_COMMIT();           // keep group counting consistent for CP_WAIT1
        }
    }

    // epilogue: stage accumulators through smem (reuse pipeline smem)
    __syncthreads();
    float* Cs = (float*)dyn_smem;       // [128][132]
#pragma unroll
    for (int i = 0; i < 2; i++)
#pragma unroll
        for (int j = 0; j < 4; j++)
            wmma::store_matrix_sync(&Cs[(wm + i * 16) * 132 + wn + j * 16], acc[i][j],
                                    132, wmma::mem_row_major);
    __syncthreads();

#pragma unroll
    for (int t = 0; t < 16; t++) {
        int q = tid + t * 256;          // 0..4095
        int row = q >> 5;
        int col = (q & 31) * 4;
        float v0 = Cs[row * 132 + col + 0] + sbias[col + 0];
        float v1 = Cs[row * 132 + col + 1] + sbias[col + 1];
        float v2 = Cs[row * 132 + col + 2] + sbias[col + 2];
        float v3 = Cs[row * 132 + col + 3] + sbias[col + 3];
        int cg = n0 + col;
        int m = m0 + row;
        if (cg < LDF) {
            *(float4*)(Out + (size_t)m * LDF + cg) = make_float4(v0, v1, v2, v3);
        }
        if (writeB && cg < LKB) {
            uint16_t h[4], l[4];
            fsplit(v0, h[0], l[0]); fsplit(v1, h[1], l[1]);
            fsplit(v2, h[2], l[2]); fsplit(v3, h[3], l[3]);
            size_t off = (size_t)m * LKB + cg;
            *(uint2*)(OutH + off) = pack4(h[0], h[1], h[2], h[3]);
            *(uint2*)(OutL + off) = pack4(l[0], l[1], l[2], l[3]);
        }
    }
}

// ---------------- mean pool -> g_mean ------------------------------------------
__global__ void mean_pool(int src) {
    const float* h = src ? g_bufB : g_bufA;
    int idx = blockIdx.x * blockDim.x + threadIdx.x;
    if (idx >= C_OUT * LDF) return;
    int c = idx / LDF, f = idx % LDF;
    float s = 0.f;
    for (int n = 0; n < N_NODES; n++)
        s += h[((size_t)n * C_OUT + c) * LDF + f];
    g_mean[idx] = s * (1.f / N_NODES);
}

__device__ __forceinline__ float gelu_exact(float x) {
    return 0.5f * x * (1.f + erff(x * 0.70710678118654752f));
}

// ---------------- fc1 + gelu ----------------------------------------------------
__global__ void fc1_kernel(const float* __restrict__ w, const float* __restrict__ b) {
    __shared__ float row[F_DIM];
    int c = blockIdx.x;
    int tid = threadIdx.x;
    for (int f = tid; f < F_DIM; f += blockDim.x) row[f] = g_mean[c * LDF + f];
    __syncthreads();
    int warp = tid >> 5, lane = tid & 31;
    for (int g = warp; g < 128; g += blockDim.x / 32) {
        const float* wr = w + (size_t)g * F_DIM;
        float acc = 0.f;
        for (int f = lane; f < F_DIM; f += 32) acc = fmaf(row[f], wr[f], acc);
#pragma unroll
        for (int o = 16; o; o >>= 1) acc += __shfl_xor_sync(0xffffffffu, acc, o);
        if (lane == 0) g_fc1[c * 128 + g] = gelu_exact(acc + b[g]);
    }
}

// ---------------- fc2 + gelu + fc3 + softmax ------------------------------------
__global__ void head_kernel(const float* __restrict__ f2w, const float* __restrict__ f2b,
                            const float* __restrict__ f3w, const float* __restrict__ f3b,
                            float* __restrict__ out) {
    __shared__ float r1[128];
    __shared__ float r2[32];
    __shared__ float r3[4];
    int c = blockIdx.x;
    int tid = threadIdx.x;
    for (int i = tid; i < 128; i += 32) r1[i] = g_fc1[c * 128 + i];
    __syncthreads();
    {
        float acc = f2b[tid];
        const float* wr = f2w + (size_t)tid * 128;
        for (int f = 0; f < 128; f++) acc = fmaf(r1[f], wr[f], acc);
        r2[tid] = gelu_exact(acc);
    }
    __syncthreads();
    if (tid < 4) {
        float a = f3b[tid];
        const float* wr = f3w + (size_t)tid * 32;
        for (int f = 0; f < 32; f++) a = fmaf(r2[f], wr[f], a);
        r3[tid] = a;
    }
    __syncthreads();
    if (tid == 0) {
        float mx = fmaxf(fmaxf(r3[0], r3[1]), fmaxf(r3[2], r3[3]));
        float e0 = expf(r3[0] - mx), e1 = expf(r3[1] - mx);
        float e2 = expf(r3[2] - mx), e3 = expf(r3[3] - mx);
        float inv = 1.f / (e0 + e1 + e2 + e3);
        out[c * 4 + 0] = e0 * inv;
        out[c * 4 + 1] = e1 * inv;
        out[c * 4 + 2] = e2 * inv;
        out[c * 4 + 3] = e3 * inv;
    }
}

// ---------------- launch --------------------------------------------------------
extern "C" void kernel_launch(void* const* d_in, const int* in_sizes, int n_in,
                              void* d_out, int out_size) {
    const float* x      = (const float*)d_in[0];
    const int*   ei     = (const int*)d_in[1];
    const float* conv_w = (const float*)d_in[2];
    const float* conv_b = (const float*)d_in[3];
    const float* wl     = (const float*)d_in[4];
    const float* wr     = (const float*)d_in[5];
    const float* sb     = (const float*)d_in[6];
    const float* f1w    = (const float*)d_in[7];
    const float* f1b    = (const float*)d_in[8];
    const float* f2w    = (const float*)d_in[9];
    const float* f2b    = (const float*)d_in[10];
    const float* f3w    = (const float*)d_in[11];
    const float* f3b    = (const float*)d_in[12];
    float* out = (float*)d_out;

    cudaFuncSetAttribute(conv1d_grouped, cudaFuncAttributeMaxDynamicSharedMemorySize, CONV_SMEM);
    cudaFuncSetAttribute(sage_gemm,      cudaFuncAttributeMaxDynamicSharedMemorySize, GEMM_SMEM);

    build_csr<<<1, 128>>>(ei);
    conv_weights<<<(NPAD * (LKB / 4) + 255) / 256, 256>>>(wl, wr);
    conv1d_grouped<<<dim3(N_NODES, 4), 256, CONV_SMEM>>>(x, conv_w, conv_b);

    // 3 SAGE layers. l0: A->B (h: hh0 -> hh1), l1: B->A (hh1 -> hh0), l2: A->B
    for (int l = 0; l < 3; l++) {
        int src = l & 1;
        sage_agg<<<M_ROWS, 128>>>(src);
        sage_gemm<<<dim3(M_TILES, N_TILES), 256, GEMM_SMEM>>>(src, l < 2 ? 1 : 0, sb);
    }

    mean_pool<<<(C_OUT * LDF + 255) / 256, 256>>>(1);
    fc1_kernel<<<256, 128>>>(f1w, f1b);
    head_kernel<<<256, 32>>>(f2w, f2b, f3w, f3b, out);
}

// round 10
// speedup vs baseline: 2.3430x; 1.4651x over previous
#include <cuda_runtime.h>
#include <cuda_fp16.h>
#include <mma.h>
#include <math.h>
#include <stdint.h>

using namespace nvcuda;

#define N_NODES 116
#define N_EDGES 1160
#define C_IN    64
#define T_IN    657
#define C_OUT   256
#define F_DIM   653
#define LDF     656                 // fp32 row stride
#define M_ROWS  (N_NODES * C_OUT)   // 29696
#define M_TILES 232                 // 29696/128
#define N_TILES 6                   // 768/128
#define NPAD    768
#define LKB     672                 // fp16 row stride (padded K, mult of 32)
#define KT_PHASE 21                 // 672/32
#define KT_TOTAL 42

#define BK      32
#define SROW    56                  // padded smem row (fp16 elems): 112B -> conflict-free LDSM
#define MAT_B   (128 * SROW * 2)    // 14336 bytes per matrix tile
#define STAGE_B (2 * MAT_B)         // 28672: A, B
#define STAGES  2
#define GEMM_SMEM 67584             // max(2*STAGE_B=57344, epilogue 128*132*4=67584)

// element offsets within a stage (fp16 units)
#define OFF_Be  7168

// single consistent dynamic-smem declaration for ALL kernels
extern __shared__ __align__(128) unsigned char dyn_smem[];

// ---------------- device scratch --------------------------------------------
__device__ __align__(16) float g_bufA[(size_t)M_ROWS * LDF];
__device__ __align__(16) float g_bufB[(size_t)M_ROWS * LDF];
__device__ __align__(16) __half g_aggh[(size_t)M_ROWS * LKB];
__device__ __align__(16) __half g_hh0[(size_t)M_ROWS * LKB];
__device__ __align__(16) __half g_hh1[(size_t)M_ROWS * LKB];
__device__ __align__(16) __half g_wlh[(size_t)NPAD * LKB];
__device__ __align__(16) __half g_wrh[(size_t)NPAD * LKB];
__device__ int   g_offs[N_NODES + 1];
__device__ int   g_list[N_EDGES];
__device__ float g_mean[C_OUT * LDF];
__device__ float g_fc1 [C_OUT * 128];

// ---------------- helpers -----------------------------------------------------
__device__ __forceinline__ uint32_t smem_u32(const void* p) {
    uint32_t a;
    asm("{ .reg .u64 t; cvta.to.shared.u64 t, %1; cvt.u32.u64 %0, t; }" : "=r"(a) : "l"(p));
    return a;
}
__device__ __forceinline__ void cpa16(uint32_t dst, const void* src) {
    asm volatile("cp.async.cg.shared.global [%0], [%1], 16;" :: "r"(dst), "l"(src));
}
#define CP_COMMIT() asm volatile("cp.async.commit_group;" ::: "memory")
#define CP_WAIT1()  asm volatile("cp.async.wait_group 1;" ::: "memory")

__device__ __forceinline__ uint2 pack4h(float a, float b, float c, float d) {
    uint16_t ha = __half_as_ushort(__float2half_rn(a));
    uint16_t hb = __half_as_ushort(__float2half_rn(b));
    uint16_t hc = __half_as_ushort(__float2half_rn(c));
    uint16_t hd = __half_as_ushort(__float2half_rn(d));
    uint2 r;
    r.x = (uint32_t)ha | ((uint32_t)hb << 16);
    r.y = (uint32_t)hc | ((uint32_t)hd << 16);
    return r;
}

// ---------------- CSR build (edge_index arrives as int32) ---------------------
__global__ void build_csr(const int* __restrict__ ei) {
    __shared__ int cnt[N_NODES + 1];
    __shared__ int offs[N_NODES + 1];
    int tid = threadIdx.x;
    for (int i = tid; i <= N_NODES; i += blockDim.x) cnt[i] = 0;
    __syncthreads();
    for (int e = tid; e < N_EDGES; e += blockDim.x) {
        int dst = min(max(ei[N_EDGES + e], 0), N_NODES - 1);
        atomicAdd(&cnt[dst], 1);
    }
    __syncthreads();
    if (tid == 0) {
        int s = 0;
        for (int i = 0; i < N_NODES; i++) { offs[i] = s; s += cnt[i]; }
        offs[N_NODES] = s;
    }
    __syncthreads();
    for (int i = tid; i <= N_NODES; i += blockDim.x) { g_offs[i] = offs[i]; cnt[i] = offs[i]; }
    __syncthreads();
    for (int e = tid; e < N_EDGES; e += blockDim.x) {
        int src = min(max(ei[e], 0), N_NODES - 1);
        int dst = min(max(ei[N_EDGES + e], 0), N_NODES - 1);
        int pos = atomicAdd(&cnt[dst], 1);
        if (pos >= 0 && pos < N_EDGES) g_list[pos] = src;
    }
}

// ---------------- weight convert -> row-major fp16 [768][672] -----------------
__global__ void conv_weights(const float* __restrict__ wl, const float* __restrict__ wr) {
    int idx = blockIdx.x * blockDim.x + threadIdx.x;   // over 768 * 168 quads
    if (idx >= NPAD * (LKB / 4)) return;
    int nrow = idx / (LKB / 4);
    int k0   = (idx % (LKB / 4)) * 4;
    size_t off = (size_t)nrow * LKB + k0;
    float a[4], b[4];
#pragma unroll
    for (int e = 0; e < 4; e++) {
        int k = k0 + e;
        a[e] = (nrow < F_DIM && k < F_DIM) ? wl[(size_t)nrow * F_DIM + k] : 0.f;
        b[e] = (nrow < F_DIM && k < F_DIM) ? wr[(size_t)nrow * F_DIM + k] : 0.f;
    }
    *(uint2*)(g_wlh + off) = pack4h(a[0], a[1], a[2], a[3]);
    *(uint2*)(g_wrh + off) = pack4h(b[0], b[1], b[2], b[3]);
}

// ---------------- grouped Conv1d -> bufA (fp32) + hh0 (fp16) ------------------
#define XS_STRIDE 660
#define CONV_SMEM ((16 * XS_STRIDE + 64 * 80) * 4)
__global__ void conv1d_grouped(const float* __restrict__ x,
                               const float* __restrict__ w,
                               const float* __restrict__ b) {
    float* smem = (float*)dyn_smem;
    float* xs = smem;
    float* ws = smem + 16 * XS_STRIDE;
    int n = blockIdx.x, g = blockIdx.y;
    int tid = threadIdx.x;

    const float* xbase = x + ((size_t)n * C_IN + (size_t)g * 16) * T_IN;
    for (int i = tid; i < 16 * T_IN; i += blockDim.x) {
        int ic = i / T_IN, t = i % T_IN;
        xs[ic * XS_STRIDE + t] = xbase[i];
    }
    for (int i = tid; i < 64 * 80; i += blockDim.x)
        ws[i] = w[(size_t)g * 64 * 80 + i];
    __syncthreads();

    for (int task = tid; task < 64 * 164; task += blockDim.x) {
        int oc = task / 164;
        int t0 = (task % 164) * 4;
        float bias = b[g * 64 + oc];
        float a0 = bias, a1 = bias, a2 = bias, a3 = bias;
        const float* wrow = &ws[oc * 80];
#pragma unroll
        for (int i = 0; i < 16; i++) {
            float4 x0 = *(const float4*)&xs[i * XS_STRIDE + t0];
            float4 x1 = *(const float4*)&xs[i * XS_STRIDE + t0 + 4];
            float xv[8] = {x0.x, x0.y, x0.z, x0.w, x1.x, x1.y, x1.z, x1.w};
#pragma unroll
            for (int k = 0; k < 5; k++) {
                float wv = wrow[i * 5 + k];
                a0 = fmaf(xv[0 + k], wv, a0);
                a1 = fmaf(xv[1 + k], wv, a1);
                a2 = fmaf(xv[2 + k], wv, a2);
                a3 = fmaf(xv[3 + k], wv, a3);
            }
        }
        float z0 = (t0 + 0 < F_DIM) ? a0 : 0.f;
        float z1 = (t0 + 1 < F_DIM) ? a1 : 0.f;
        float z2 = (t0 + 2 < F_DIM) ? a2 : 0.f;
        float z3 = (t0 + 3 < F_DIM) ? a3 : 0.f;
        int row = n * C_OUT + g * 64 + oc;
        float* out = &g_bufA[(size_t)row * LDF + t0];
        out[0] = z0; out[1] = z1; out[2] = z2; out[3] = z3;
        size_t off = (size_t)row * LKB + t0;
        *(uint2*)(g_hh0 + off) = pack4h(z0, z1, z2, z3);
    }
    // zero the fp16 K-pad tail (cols 656..671) for this block's 64 rows
    for (int i = tid; i < 64 * 4; i += blockDim.x) {
        int oc = i / 4;
        int c0 = 656 + (i % 4) * 4;
        int row = n * C_OUT + g * 64 + oc;
        size_t off = (size_t)row * LKB + c0;
        *(uint2*)(g_hh0 + off) = make_uint2(0u, 0u);
    }
}

// ---------------- SAGE max-aggregation -> aggh (fp16 row-major) ---------------
__global__ void sage_agg(int src) {
    const float* h = src ? g_bufB : g_bufA;
    int row = blockIdx.x;          // n*256 + c
    int n = row >> 8;
    int c = row & 255;
    int beg = g_offs[n], end = g_offs[n + 1];
    size_t obase = (size_t)row * LKB;
    for (int v = threadIdx.x; v < LKB / 4; v += blockDim.x) {
        int f0 = v * 4;
        float4 m = make_float4(0.f, 0.f, 0.f, 0.f);
        if (f0 < LDF && end > beg) {
            m = make_float4(-3.4e38f, -3.4e38f, -3.4e38f, -3.4e38f);
            for (int e = beg; e < end; e++) {
                int s = g_list[e];
                float4 t = *(const float4*)(h + ((size_t)s * C_OUT + c) * LDF + f0);
                m.x = fmaxf(m.x, t.x); m.y = fmaxf(m.y, t.y);
                m.z = fmaxf(m.z, t.z); m.w = fmaxf(m.w, t.w);
            }
        }
        *(uint2*)(g_aggh + obase + f0) = pack4h(m.x, m.y, m.z, m.w);
    }
}

// ---------------- WMMA fused SAGE GEMM ----------------------------------------
// C[128x128] = agg@Wl^T + h@Wr^T, plain fp16 operands, fp32 accumulate.
// 2-stage cp.async pipeline (BK=32), smem rows padded to 112B (conflict-free LDSM).
__device__ __forceinline__ void stage_copy(uint32_t sbase, int tid,
                                           const __half* pA, const __half* pB) {
#pragma unroll
    for (int half_ = 0; half_ < 2; half_++) {
        int c = tid + half_ * 256;      // 0..511
        int row = c >> 2;               // 0..127
        int col = (c & 3) << 3;         // 0,8,16,24
        uint32_t so = (uint32_t)row * (SROW * 2) + col * 2;
        size_t go = (size_t)row * LKB + col;
        cpa16(sbase +         so, pA + go);
        cpa16(sbase + MAT_B + so, pB + go);
    }
    CP_COMMIT();
}

__global__ void __launch_bounds__(256, 2) sage_gemm(int src, int writeB,
                                                    const float* __restrict__ bias) {
    __shared__ float sbias[128];
    const int tid = threadIdx.x;
    const int wid = tid >> 5;
    const int m0 = blockIdx.x * 128;
    const int n0 = blockIdx.y * 128;

    const __half* AArr[2] = { g_aggh, src ? g_hh1 : g_hh0 };
    const __half* BArr[2] = { g_wlh, g_wrh };
    float*   Out  = src ? g_bufA : g_bufB;
    __half*  OutH = src ? g_hh0 : g_hh1;

    if (tid < 128) {
        int cg = n0 + tid;
        sbias[tid] = (cg < F_DIM) ? bias[cg] : 0.f;
    }

    const uint32_t smem_base = smem_u32(dyn_smem);

    // prologue: stages 0,1 (both phase 0 since KT_PHASE=21 > 1)
#pragma unroll
    for (int p = 0; p < 2; p++) {
        int k0 = p * BK;
        stage_copy(smem_base + p * STAGE_B, tid,
                   AArr[0] + (size_t)m0 * LKB + k0,
                   BArr[0] + (size_t)n0 * LKB + k0);
    }

    const int wm = (wid & 3) * 32;      // warp m offset within tile
    const int wn = (wid >> 2) * 64;     // warp n offset within tile

    wmma::fragment<wmma::accumulator, 16, 16, 16, float> acc[2][4];
#pragma unroll
    for (int i = 0; i < 2; i++)
#pragma unroll
        for (int j = 0; j < 4; j++) wmma::fill_fragment(acc[i][j], 0.f);

    for (int kt = 0; kt < KT_TOTAL; kt++) {
        CP_WAIT1();
        __syncthreads();
        const __half* sA = (const __half*)(dyn_smem + (kt & 1) * STAGE_B);
        const __half* sB = sA + OFF_Be;
#pragma unroll
        for (int ks = 0; ks < 2; ks++) {
            wmma::fragment<wmma::matrix_a, 16, 16, 16, __half, wmma::row_major> af[2];
            wmma::fragment<wmma::matrix_b, 16, 16, 16, __half, wmma::col_major> bf[4];
#pragma unroll
            for (int i = 0; i < 2; i++) {
                const __half* pa = sA + (wm + i * 16) * SROW + ks * 16;
                wmma::load_matrix_sync(af[i], pa, SROW);
            }
#pragma unroll
            for (int j = 0; j < 4; j++) {
                const __half* pb = sB + (wn + j * 16) * SROW + ks * 16;
                wmma::load_matrix_sync(bf[j], pb, SROW);
            }
#pragma unroll
            for (int i = 0; i < 2; i++)
#pragma unroll
                for (int j = 0; j < 4; j++)
                    wmma::mma_sync(acc[i][j], af[i], bf[j], acc[i][j]);
        }
        __syncthreads();           // all warps done reading stage kt&1
        int nk = kt + 2;
        if (nk < KT_TOTAL) {
            int ph = (nk >= KT_PHASE) ? 1 : 0;
            int k0 = (nk - ph * KT_PHASE) * BK;
            stage_copy(smem_base + (kt & 1) * STAGE_B, tid,
                       AArr[ph] + (size_t)m0 * LKB + k0,
                       BArr[ph] + (size_t)n0 * LKB + k0);
        } else {
            CP_COMMIT();           // keep group counting consistent for CP_WAIT1
        }
    }

    // epilogue: stage accumulators through smem (reuse pipeline smem)
    __syncthreads();
    float* Cs = (float*)dyn_smem;       // [128][132]
#pragma unroll
    for (int i = 0; i < 2; i++)
#pragma unroll
        for (int j = 0; j < 4; j++)
            wmma::store_matrix_sync(&Cs[(wm + i * 16) * 132 + wn + j * 16], acc[i][j],
                                    132, wmma::mem_row_major);
    __syncthreads();

#pragma unroll
    for (int t = 0; t < 16; t++) {
        int q = tid + t * 256;          // 0..4095
        int row = q >> 5;
        int col = (q & 31) * 4;
        float v0 = Cs[row * 132 + col + 0] + sbias[col + 0];
        float v1 = Cs[row * 132 + col + 1] + sbias[col + 1];
        float v2 = Cs[row * 132 + col + 2] + sbias[col + 2];
        float v3 = Cs[row * 132 + col + 3] + sbias[col + 3];
        int cg = n0 + col;
        int m = m0 + row;
        if (cg < LDF) {
            *(float4*)(Out + (size_t)m * LDF + cg) = make_float4(v0, v1, v2, v3);
        }
        if (writeB && cg < LKB) {
            *(uint2*)(OutH + (size_t)m * LKB + cg) = pack4h(v0, v1, v2, v3);
        }
    }
}

// ---------------- mean pool -> g_mean ------------------------------------------
__global__ void mean_pool(int src) {
    const float* h = src ? g_bufB : g_bufA;
    int idx = blockIdx.x * blockDim.x + threadIdx.x;
    if (idx >= C_OUT * LDF) return;
    int c = idx / LDF, f = idx % LDF;
    float s = 0.f;
    for (int n = 0; n < N_NODES; n++)
        s += h[((size_t)n * C_OUT + c) * LDF + f];
    g_mean[idx] = s * (1.f / N_NODES);
}

__device__ __forceinline__ float gelu_exact(float x) {
    return 0.5f * x * (1.f + erff(x * 0.70710678118654752f));
}

// ---------------- fc1 + gelu ----------------------------------------------------
__global__ void fc1_kernel(const float* __restrict__ w, const float* __restrict__ b) {
    __shared__ float row[F_DIM];
    int c = blockIdx.x;
    int tid = threadIdx.x;
    for (int f = tid; f < F_DIM; f += blockDim.x) row[f] = g_mean[c * LDF + f];
    __syncthreads();
    int warp = tid >> 5, lane = tid & 31;
    for (int g = warp; g < 128; g += blockDim.x / 32) {
        const float* wr = w + (size_t)g * F_DIM;
        float acc = 0.f;
        for (int f = lane; f < F_DIM; f += 32) acc = fmaf(row[f], wr[f], acc);
#pragma unroll
        for (int o = 16; o; o >>= 1) acc += __shfl_xor_sync(0xffffffffu, acc, o);
        if (lane == 0) g_fc1[c * 128 + g] = gelu_exact(acc + b[g]);
    }
}

// ---------------- fc2 + gelu + fc3 + softmax ------------------------------------
__global__ void head_kernel(const float* __restrict__ f2w, const float* __restrict__ f2b,
                            const float* __restrict__ f3w, const float* __restrict__ f3b,
                            float* __restrict__ out) {
    __shared__ float r1[128];
    __shared__ float r2[32];
    __shared__ float r3[4];
    int c = blockIdx.x;
    int tid = threadIdx.x;
    for (int i = tid; i < 128; i += 32) r1[i] = g_fc1[c * 128 + i];
    __syncthreads();
    {
        float acc = f2b[tid];
        const float* wr = f2w + (size_t)tid * 128;
        for (int f = 0; f < 128; f++) acc = fmaf(r1[f], wr[f], acc);
        r2[tid] = gelu_exact(acc);
    }
    __syncthreads();
    if (tid < 4) {
        float a = f3b[tid];
        const float* wr = f3w + (size_t)tid * 32;
        for (int f = 0; f < 32; f++) a = fmaf(r2[f], wr[f], a);
        r3[tid] = a;
    }
    __syncthreads();
    if (tid == 0) {
        float mx = fmaxf(fmaxf(r3[0], r3[1]), fmaxf(r3[2], r3[3]));
        float e0 = expf(r3[0] - mx), e1 = expf(r3[1] - mx);
        float e2 = expf(r3[2] - mx), e3 = expf(r3[3] - mx);
        float inv = 1.f / (e0 + e1 + e2 + e3);
        out[c * 4 + 0] = e0 * inv;
        out[c * 4 + 1] = e1 * inv;
        out[c * 4 + 2] = e2 * inv;
        out[c * 4 + 3] = e3 * inv;
    }
}

// ---------------- launch --------------------------------------------------------
extern "C" void kernel_launch(void* const* d_in, const int* in_sizes, int n_in,
                              void* d_out, int out_size) {
    const float* x      = (const float*)d_in[0];
    const int*   ei     = (const int*)d_in[1];
    const float* conv_w = (const float*)d_in[2];
    const float* conv_b = (const float*)d_in[3];
    const float* wl     = (const float*)d_in[4];
    const float* wr     = (const float*)d_in[5];
    const float* sb     = (const float*)d_in[6];
    const float* f1w    = (const float*)d_in[7];
    const float* f1b    = (const float*)d_in[8];
    const float* f2w    = (const float*)d_in[9];
    const float* f2b    = (const float*)d_in[10];
    const float* f3w    = (const float*)d_in[11];
    const float* f3b    = (const float*)d_in[12];
    float* out = (float*)d_out;

    cudaFuncSetAttribute(conv1d_grouped, cudaFuncAttributeMaxDynamicSharedMemorySize, CONV_SMEM);
    cudaFuncSetAttribute(sage_gemm,      cudaFuncAttributeMaxDynamicSharedMemorySize, GEMM_SMEM);

    build_csr<<<1, 128>>>(ei);
    conv_weights<<<(NPAD * (LKB / 4) + 255) / 256, 256>>>(wl, wr);
    conv1d_grouped<<<dim3(N_NODES, 4), 256, CONV_SMEM>>>(x, conv_w, conv_b);

    // 3 SAGE layers. l0: A->B (h: hh0 -> hh1), l1: B->A (hh1 -> hh0), l2: A->B
    for (int l = 0; l < 3; l++) {
        int src = l & 1;
        sage_agg<<<M_ROWS, 128>>>(src);
        sage_gemm<<<dim3(M_TILES, N_TILES), 256, GEMM_SMEM>>>(src, l < 2 ? 1 : 0, sb);
    }

    mean_pool<<<(C_OUT * LDF + 255) / 256, 256>>>(1);
    fc1_kernel<<<256, 128>>>(f1w, f1b);
    head_kernel<<<256, 32>>>(f2w, f2b, f3w, f3b, out);
}

// round 11
// speedup vs baseline: 2.7150x; 1.1588x over previous
#include <cuda_runtime.h>
#include <cuda_fp16.h>
#include <mma.h>
#include <math.h>
#include <stdint.h>

using namespace nvcuda;

#define N_NODES 116
#define N_EDGES 1160
#define C_IN    64
#define T_IN    657
#define C_OUT   256
#define F_DIM   653
#define LDF     656                 // fp32 row stride (final layer only)
#define M_ROWS  (N_NODES * C_OUT)   // 29696
#define M_TILES 232                 // 29696/128
#define N_TILES 7                   // 7 * 96 = 672
#define BN      96
#define NPAD    672
#define LKB     672                 // fp16 row stride (padded K, mult of 32)
#define KT_PHASE 21                 // 672/32
#define KT_TOTAL 42

#define BK      32
#define SROW    56                  // padded smem row (fp16 elems): 112B -> conflict-free LDSM
#define A_B     (128 * 112)         // 14336 bytes (A tile)
#define B_B     (96 * 112)          // 10752 bytes (B tile)
#define STAGE_B (A_B + B_B)         // 25088
#define GEMM_SMEM 51200             // max(2*STAGE_B=50176, epilogue 128*100*4=51200)

#define OFF_Be  7168                // A_B/2 in fp16 elements

// single consistent dynamic-smem declaration for ALL kernels
extern __shared__ __align__(128) unsigned char dyn_smem[];

// ---------------- device scratch --------------------------------------------
__device__ __align__(16) float g_bufB[(size_t)M_ROWS * LDF];   // final fp32 activations
__device__ __align__(16) __half g_aggh[(size_t)M_ROWS * LKB];
__device__ __align__(16) __half g_hh0[(size_t)M_ROWS * LKB];
__device__ __align__(16) __half g_hh1[(size_t)M_ROWS * LKB];
__device__ __align__(16) __half g_wlh[(size_t)NPAD * LKB];
__device__ __align__(16) __half g_wrh[(size_t)NPAD * LKB];
__device__ int   g_offs[N_NODES + 1];
__device__ int   g_list[N_EDGES];
__device__ float g_mean[C_OUT * LDF];
__device__ float g_fc1 [C_OUT * 128];

// ---------------- helpers -----------------------------------------------------
__device__ __forceinline__ uint32_t smem_u32(const void* p) {
    uint32_t a;
    asm("{ .reg .u64 t; cvta.to.shared.u64 t, %1; cvt.u32.u64 %0, t; }" : "=r"(a) : "l"(p));
    return a;
}
__device__ __forceinline__ void cpa16(uint32_t dst, const void* src) {
    asm volatile("cp.async.cg.shared.global [%0], [%1], 16;" :: "r"(dst), "l"(src));
}
#define CP_COMMIT() asm volatile("cp.async.commit_group;" ::: "memory")
#define CP_WAIT1()  asm volatile("cp.async.wait_group 1;" ::: "memory")

__device__ __forceinline__ uint2 pack4h(float a, float b, float c, float d) {
    uint16_t ha = __half_as_ushort(__float2half_rn(a));
    uint16_t hb = __half_as_ushort(__float2half_rn(b));
    uint16_t hc = __half_as_ushort(__float2half_rn(c));
    uint16_t hd = __half_as_ushort(__float2half_rn(d));
    uint2 r;
    r.x = (uint32_t)ha | ((uint32_t)hb << 16);
    r.y = (uint32_t)hc | ((uint32_t)hd << 16);
    return r;
}

// ---------------- CSR build (edge_index arrives as int32) ---------------------
__global__ void build_csr(const int* __restrict__ ei) {
    __shared__ int cnt[N_NODES + 1];
    __shared__ int offs[N_NODES + 1];
    int tid = threadIdx.x;
    for (int i = tid; i <= N_NODES; i += blockDim.x) cnt[i] = 0;
    __syncthreads();
    for (int e = tid; e < N_EDGES; e += blockDim.x) {
        int dst = min(max(ei[N_EDGES + e], 0), N_NODES - 1);
        atomicAdd(&cnt[dst], 1);
    }
    __syncthreads();
    if (tid == 0) {
        int s = 0;
        for (int i = 0; i < N_NODES; i++) { offs[i] = s; s += cnt[i]; }
        offs[N_NODES] = s;
    }
    __syncthreads();
    for (int i = tid; i <= N_NODES; i += blockDim.x) { g_offs[i] = offs[i]; cnt[i] = offs[i]; }
    __syncthreads();
    for (int e = tid; e < N_EDGES; e += blockDim.x) {
        int src = min(max(ei[e], 0), N_NODES - 1);
        int dst = min(max(ei[N_EDGES + e], 0), N_NODES - 1);
        int pos = atomicAdd(&cnt[dst], 1);
        if (pos >= 0 && pos < N_EDGES) g_list[pos] = src;
    }
}

// ---------------- weight convert -> row-major fp16 [672][672] -----------------
__global__ void conv_weights(const float* __restrict__ wl, const float* __restrict__ wr) {
    int idx = blockIdx.x * blockDim.x + threadIdx.x;   // over 672 * 168 quads
    if (idx >= NPAD * (LKB / 4)) return;
    int nrow = idx / (LKB / 4);
    int k0   = (idx % (LKB / 4)) * 4;
    size_t off = (size_t)nrow * LKB + k0;
    float a[4], b[4];
#pragma unroll
    for (int e = 0; e < 4; e++) {
        int k = k0 + e;
        a[e] = (nrow < F_DIM && k < F_DIM) ? wl[(size_t)nrow * F_DIM + k] : 0.f;
        b[e] = (nrow < F_DIM && k < F_DIM) ? wr[(size_t)nrow * F_DIM + k] : 0.f;
    }
    *(uint2*)(g_wlh + off) = pack4h(a[0], a[1], a[2], a[3]);
    *(uint2*)(g_wrh + off) = pack4h(b[0], b[1], b[2], b[3]);
}

// ---------------- grouped Conv1d -> hh0 (fp16 only) ---------------------------
#define XS_STRIDE 660
#define CONV_SMEM ((16 * XS_STRIDE + 64 * 80) * 4)
__global__ void conv1d_grouped(const float* __restrict__ x,
                               const float* __restrict__ w,
                               const float* __restrict__ b) {
    float* smem = (float*)dyn_smem;
    float* xs = smem;
    float* ws = smem + 16 * XS_STRIDE;
    int n = blockIdx.x, g = blockIdx.y;
    int tid = threadIdx.x;

    const float* xbase = x + ((size_t)n * C_IN + (size_t)g * 16) * T_IN;
    for (int i = tid; i < 16 * T_IN; i += blockDim.x) {
        int ic = i / T_IN, t = i % T_IN;
        xs[ic * XS_STRIDE + t] = xbase[i];
    }
    for (int i = tid; i < 64 * 80; i += blockDim.x)
        ws[i] = w[(size_t)g * 64 * 80 + i];
    __syncthreads();

    for (int task = tid; task < 64 * 164; task += blockDim.x) {
        int oc = task / 164;
        int t0 = (task % 164) * 4;
        float bias = b[g * 64 + oc];
        float a0 = bias, a1 = bias, a2 = bias, a3 = bias;
        const float* wrow = &ws[oc * 80];
#pragma unroll
        for (int i = 0; i < 16; i++) {
            float4 x0 = *(const float4*)&xs[i * XS_STRIDE + t0];
            float4 x1 = *(const float4*)&xs[i * XS_STRIDE + t0 + 4];
            float xv[8] = {x0.x, x0.y, x0.z, x0.w, x1.x, x1.y, x1.z, x1.w};
#pragma unroll
            for (int k = 0; k < 5; k++) {
                float wv = wrow[i * 5 + k];
                a0 = fmaf(xv[0 + k], wv, a0);
                a1 = fmaf(xv[1 + k], wv, a1);
                a2 = fmaf(xv[2 + k], wv, a2);
                a3 = fmaf(xv[3 + k], wv, a3);
            }
        }
        float z0 = (t0 + 0 < F_DIM) ? a0 : 0.f;
        float z1 = (t0 + 1 < F_DIM) ? a1 : 0.f;
        float z2 = (t0 + 2 < F_DIM) ? a2 : 0.f;
        float z3 = (t0 + 3 < F_DIM) ? a3 : 0.f;
        int row = n * C_OUT + g * 64 + oc;
        size_t off = (size_t)row * LKB + t0;
        *(uint2*)(g_hh0 + off) = pack4h(z0, z1, z2, z3);
    }
    // zero the fp16 K-pad tail (cols 656..671) for this block's 64 rows
    for (int i = tid; i < 64 * 4; i += blockDim.x) {
        int oc = i / 4;
        int c0 = 656 + (i % 4) * 4;
        int row = n * C_OUT + g * 64 + oc;
        size_t off = (size_t)row * LKB + c0;
        *(uint2*)(g_hh0 + off) = make_uint2(0u, 0u);
    }
}

// ---------------- SAGE max-aggregation (fp16 in -> fp16 out) ------------------
__global__ void sage_agg(int src) {
    const __half* h = src ? g_hh1 : g_hh0;
    int row = blockIdx.x;          // n*256 + c
    int n = row >> 8;
    int c = row & 255;
    int beg = g_offs[n], end = g_offs[n + 1];
    size_t obase = (size_t)row * LKB;
    const __half2 NEG_INF2 = __halves2half2(__ushort_as_half(0xFC00u),
                                            __ushort_as_half(0xFC00u));
    for (int v = threadIdx.x; v < LKB / 4; v += blockDim.x) {
        int f0 = v * 4;
        uint2 outv = make_uint2(0u, 0u);
        if (end > beg) {
            __half2 m0 = NEG_INF2, m1 = NEG_INF2;
            for (int e = beg; e < end; e++) {
                int s = g_list[e];
                uint2 t = *(const uint2*)(h + ((size_t)s * C_OUT + c) * LKB + f0);
                m0 = __hmax2(m0, *(__half2*)&t.x);
                m1 = __hmax2(m1, *(__half2*)&t.y);
            }
            outv.x = *(uint32_t*)&m0;
            outv.y = *(uint32_t*)&m1;
        }
        *(uint2*)(g_aggh + obase + f0) = outv;
    }
}

// ---------------- WMMA fused SAGE GEMM ----------------------------------------
// C[128x96] = agg@Wl^T + h@Wr^T, fp16 operands, fp32 accumulate.
// 2-stage cp.async pipeline (BK=32), smem rows padded to 112B (conflict-free LDSM).
__device__ __forceinline__ void stage_copy(uint32_t sbase, int tid,
                                           const __half* pA, const __half* pB) {
#pragma unroll
    for (int t = 0; t < 4; t++) {
        int idx = tid + t * 256;            // 0..1023, 896 used
        if (idx < 512) {                    // A: 128 rows x 4 chunks
            int row = idx >> 2, c = idx & 3;
            cpa16(sbase + row * 112 + c * 16, pA + (size_t)row * LKB + c * 8);
        } else if (idx < 896) {             // B: 96 rows x 4 chunks
            int j = idx - 512;
            int row = j >> 2, c = j & 3;
            cpa16(sbase + A_B + row * 112 + c * 16, pB + (size_t)row * LKB + c * 8);
        }
    }
    CP_COMMIT();
}

__global__ void __launch_bounds__(256, 2) sage_gemm(int src, int writeH,
                                                    const float* __restrict__ bias) {
    __shared__ float sbias[BN];
    const int tid = threadIdx.x;
    const int wid = tid >> 5;
    const int m0 = blockIdx.x * 128;
    const int n0 = blockIdx.y * BN;

    const __half* AArr[2] = { g_aggh, src ? g_hh1 : g_hh0 };
    const __half* BArr[2] = { g_wlh, g_wrh };
    __half* OutH = src ? g_hh0 : g_hh1;

    if (tid < BN) {
        int cg = n0 + tid;
        sbias[tid] = (cg < F_DIM) ? bias[cg] : 0.f;
    }

    const uint32_t smem_base = smem_u32(dyn_smem);

    // prologue: stages 0,1 (both phase 0 since KT_PHASE=21 > 1)
#pragma unroll
    for (int p = 0; p < 2; p++) {
        int k0 = p * BK;
        stage_copy(smem_base + p * STAGE_B, tid,
                   AArr[0] + (size_t)m0 * LKB + k0,
                   BArr[0] + (size_t)n0 * LKB + k0);
    }

    const int wm = (wid & 3) * 32;      // 4 m-warps x 32
    const int wn = (wid >> 2) * 48;     // 2 n-warps x 48

    wmma::fragment<wmma::accumulator, 16, 16, 16, float> acc[2][3];
#pragma unroll
    for (int i = 0; i < 2; i++)
#pragma unroll
        for (int j = 0; j < 3; j++) wmma::fill_fragment(acc[i][j], 0.f);

    for (int kt = 0; kt < KT_TOTAL; kt++) {
        CP_WAIT1();
        __syncthreads();
        const __half* sA = (const __half*)(dyn_smem + (kt & 1) * STAGE_B);
        const __half* sB = sA + OFF_Be;
#pragma unroll
        for (int ks = 0; ks < 2; ks++) {
            wmma::fragment<wmma::matrix_a, 16, 16, 16, __half, wmma::row_major> af[2];
            wmma::fragment<wmma::matrix_b, 16, 16, 16, __half, wmma::col_major> bf[3];
#pragma unroll
            for (int i = 0; i < 2; i++)
                wmma::load_matrix_sync(af[i], sA + (wm + i * 16) * SROW + ks * 16, SROW);
#pragma unroll
            for (int j = 0; j < 3; j++)
                wmma::load_matrix_sync(bf[j], sB + (wn + j * 16) * SROW + ks * 16, SROW);
#pragma unroll
            for (int i = 0; i < 2; i++)
#pragma unroll
                for (int j = 0; j < 3; j++)
                    wmma::mma_sync(acc[i][j], af[i], bf[j], acc[i][j]);
        }
        __syncthreads();           // all warps done reading stage kt&1
        int nk = kt + 2;
        if (nk < KT_TOTAL) {
            int ph = (nk >= KT_PHASE) ? 1 : 0;
            int k0 = (nk - ph * KT_PHASE) * BK;
            stage_copy(smem_base + (kt & 1) * STAGE_B, tid,
                       AArr[ph] + (size_t)m0 * LKB + k0,
                       BArr[ph] + (size_t)n0 * LKB + k0);
        } else {
            CP_COMMIT();           // keep group counting consistent for CP_WAIT1
        }
    }

    // epilogue: stage accumulators through smem (reuse pipeline smem)
    __syncthreads();
    float* Cs = (float*)dyn_smem;       // [128][100]
#pragma unroll
    for (int i = 0; i < 2; i++)
#pragma unroll
        for (int j = 0; j < 3; j++)
            wmma::store_matrix_sync(&Cs[(wm + i * 16) * 100 + wn + j * 16], acc[i][j],
                                    100, wmma::mem_row_major);
    __syncthreads();

#pragma unroll
    for (int t = 0; t < 12; t++) {
        int q = tid + t * 256;          // 0..3071 quads (128 x 24)
        int row = q / 24;
        int col = (q % 24) * 4;
        float v0 = Cs[row * 100 + col + 0] + sbias[col + 0];
        float v1 = Cs[row * 100 + col + 1] + sbias[col + 1];
        float v2 = Cs[row * 100 + col + 2] + sbias[col + 2];
        float v3 = Cs[row * 100 + col + 3] + sbias[col + 3];
        int cg = n0 + col;
        int m = m0 + row;
        if (writeH) {
            *(uint2*)(OutH + (size_t)m * LKB + cg) = pack4h(v0, v1, v2, v3);
        } else if (cg < LDF) {
            *(float4*)(g_bufB + (size_t)m * LDF + cg) = make_float4(v0, v1, v2, v3);
        }
    }
}

// ---------------- mean pool -> g_mean ------------------------------------------
__global__ void mean_pool() {
    int idx = blockIdx.x * blockDim.x + threadIdx.x;
    if (idx >= C_OUT * LDF) return;
    int c = idx / LDF, f = idx % LDF;
    float s = 0.f;
    for (int n = 0; n < N_NODES; n++)
        s += g_bufB[((size_t)n * C_OUT + c) * LDF + f];
    g_mean[idx] = s * (1.f / N_NODES);
}

__device__ __forceinline__ float gelu_exact(float x) {
    return 0.5f * x * (1.f + erff(x * 0.70710678118654752f));
}

// ---------------- fc1 + gelu ----------------------------------------------------
__global__ void fc1_kernel(const float* __restrict__ w, const float* __restrict__ b) {
    __shared__ float row[F_DIM];
    int c = blockIdx.x;
    int tid = threadIdx.x;
    for (int f = tid; f < F_DIM; f += blockDim.x) row[f] = g_mean[c * LDF + f];
    __syncthreads();
    int warp = tid >> 5, lane = tid & 31;
    for (int g = warp; g < 128; g += blockDim.x / 32) {
        const float* wr = w + (size_t)g * F_DIM;
        float acc = 0.f;
        for (int f = lane; f < F_DIM; f += 32) acc = fmaf(row[f], wr[f], acc);
#pragma unroll
        for (int o = 16; o; o >>= 1) acc += __shfl_xor_sync(0xffffffffu, acc, o);
        if (lane == 0) g_fc1[c * 128 + g] = gelu_exact(acc + b[g]);
    }
}

// ---------------- fc2 + gelu + fc3 + softmax ------------------------------------
__global__ void head_kernel(const float* __restrict__ f2w, const float* __restrict__ f2b,
                            const float* __restrict__ f3w, const float* __restrict__ f3b,
                            float* __restrict__ out) {
    __shared__ float r1[128];
    __shared__ float r2[32];
    __shared__ float r3[4];
    int c = blockIdx.x;
    int tid = threadIdx.x;
    for (int i = tid; i < 128; i += 32) r1[i] = g_fc1[c * 128 + i];
    __syncthreads();
    {
        float acc = f2b[tid];
        const float* wr = f2w + (size_t)tid * 128;
        for (int f = 0; f < 128; f++) acc = fmaf(r1[f], wr[f], acc);
        r2[tid] = gelu_exact(acc);
    }
    __syncthreads();
    if (tid < 4) {
        float a = f3b[tid];
        const float* wr = f3w + (size_t)tid * 32;
        for (int f = 0; f < 32; f++) a = fmaf(r2[f], wr[f], a);
        r3[tid] = a;
    }
    __syncthreads();
    if (tid == 0) {
        float mx = fmaxf(fmaxf(r3[0], r3[1]), fmaxf(r3[2], r3[3]));
        float e0 = expf(r3[0] - mx), e1 = expf(r3[1] - mx);
        float e2 = expf(r3[2] - mx), e3 = expf(r3[3] - mx);
        float inv = 1.f / (e0 + e1 + e2 + e3);
        out[c * 4 + 0] = e0 * inv;
        out[c * 4 + 1] = e1 * inv;
        out[c * 4 + 2] = e2 * inv;
        out[c * 4 + 3] = e3 * inv;
    }
}

// ---------------- launch --------------------------------------------------------
extern "C" void kernel_launch(void* const* d_in, const int* in_sizes, int n_in,
                              void* d_out, int out_size) {
    const float* x      = (const float*)d_in[0];
    const int*   ei     = (const int*)d_in[1];
    const float* conv_w = (const float*)d_in[2];
    const float* conv_b = (const float*)d_in[3];
    const float* wl     = (const float*)d_in[4];
    const float* wr     = (const float*)d_in[5];
    const float* sb     = (const float*)d_in[6];
    const float* f1w    = (const float*)d_in[7];
    const float* f1b    = (const float*)d_in[8];
    const float* f2w    = (const float*)d_in[9];
    const float* f2b    = (const float*)d_in[10];
    const float* f3w    = (const float*)d_in[11];
    const float* f3b    = (const float*)d_in[12];
    float* out = (float*)d_out;

    cudaFuncSetAttribute(conv1d_grouped, cudaFuncAttributeMaxDynamicSharedMemorySize, CONV_SMEM);
    cudaFuncSetAttribute(sage_gemm,      cudaFuncAttributeMaxDynamicSharedMemorySize, GEMM_SMEM);

    build_csr<<<1, 128>>>(ei);
    conv_weights<<<(NPAD * (LKB / 4) + 255) / 256, 256>>>(wl, wr);
    conv1d_grouped<<<dim3(N_NODES, 4), 256, CONV_SMEM>>>(x, conv_w, conv_b);

    // 3 SAGE layers (fp16 ping-pong hh0 <-> hh1). Layer 2 emits fp32 to g_bufB.
    for (int l = 0; l < 3; l++) {
        int src = l & 1;
        sage_agg<<<M_ROWS, 128>>>(src);
        sage_gemm<<<dim3(M_TILES, N_TILES), 256, GEMM_SMEM>>>(src, l < 2 ? 1 : 0, sb);
    }

    mean_pool<<<(C_OUT * LDF + 255) / 256, 256>>>();
    fc1_kernel<<<256, 128>>>(f1w, f1b);
    head_kernel<<<256, 32>>>(f2w, f2b, f3w, f3b, out);
}

// round 12
// speedup vs baseline: 2.9892x; 1.1010x over previous
#include <cuda_runtime.h>
#include <cuda_fp16.h>
#include <mma.h>
#include <math.h>
#include <stdint.h>

using namespace nvcuda;

#define N_NODES 116
#define N_EDGES 1160
#define C_IN    64
#define T_IN    657
#define C_OUT   256
#define F_DIM   653
#define LDF     656
#define M_ROWS  (N_NODES * C_OUT)   // 29696
#define M_TILES 232                 // 29696/128
#define N_TILES 7                   // 7 * 96 = 672
#define BN      96
#define NPAD    672
#define LKB     672                 // fp16 row stride (padded K)
#define KT_PHASE 21                 // 672/32
#define KT_TOTAL 42

#define BK      32
#define SROW    56                  // padded smem row (fp16): 112B -> conflict-free LDSM
#define A_B     (128 * 112)         // 14336
#define B_B     (96 * 112)          // 10752
#define STAGE_B (A_B + B_B)         // 25088
#define GEMM_SMEM 51200             // max(2*STAGE_B=50176, epilogue 128*100*4)
#define OFF_Be  7168

// conv-as-GEMM constants
#define TPN     768                 // padded t per node (6 * 128)
#define CK      80                  // conv K = 16 ic * 5 taps
#define CSROW   88                  // row stride (fp16) for im2col + conv smem (176B, conflict-free)
#define CGEMM_SMEM 33792            // A 128*176 + B 64*176 = 33792; Cs2 64*132*4 = 33792

extern __shared__ __align__(128) unsigned char dyn_smem[];

// ---------------- device scratch --------------------------------------------
__device__ __align__(16) __half g_aggh[(size_t)M_ROWS * LKB];
__device__ __align__(16) __half g_hh0[(size_t)M_ROWS * LKB];
__device__ __align__(16) __half g_hh1[(size_t)M_ROWS * LKB];
__device__ __align__(16) __half g_wlh[(size_t)NPAD * LKB];
__device__ __align__(16) __half g_wrh[(size_t)NPAD * LKB];
__device__ __align__(16) __half g_im [(size_t)4 * N_NODES * TPN * CSROW];
__device__ __align__(16) __half g_cwh[(size_t)C_OUT * CSROW];
__device__ int   g_offs[N_NODES + 1];
__device__ int   g_list[N_EDGES];
__device__ float g_mean[C_OUT * LDF];
__device__ float g_fc1 [C_OUT * 128];

// ---------------- helpers -----------------------------------------------------
__device__ __forceinline__ uint32_t smem_u32(const void* p) {
    uint32_t a;
    asm("{ .reg .u64 t; cvta.to.shared.u64 t, %1; cvt.u32.u64 %0, t; }" : "=r"(a) : "l"(p));
    return a;
}
__device__ __forceinline__ void cpa16(uint32_t dst, const void* src) {
    asm volatile("cp.async.cg.shared.global [%0], [%1], 16;" :: "r"(dst), "l"(src));
}
#define CP_COMMIT() asm volatile("cp.async.commit_group;" ::: "memory")
#define CP_WAIT1()  asm volatile("cp.async.wait_group 1;" ::: "memory")
#define CP_WAIT0()  asm volatile("cp.async.wait_group 0;" ::: "memory")

__device__ __forceinline__ uint2 pack4h(float a, float b, float c, float d) {
    uint16_t ha = __half_as_ushort(__float2half_rn(a));
    uint16_t hb = __half_as_ushort(__float2half_rn(b));
    uint16_t hc = __half_as_ushort(__float2half_rn(c));
    uint16_t hd = __half_as_ushort(__float2half_rn(d));
    uint2 r;
    r.x = (uint32_t)ha | ((uint32_t)hb << 16);
    r.y = (uint32_t)hc | ((uint32_t)hd << 16);
    return r;
}

// ---------------- CSR build (edge_index arrives as int32) ---------------------
__global__ void build_csr(const int* __restrict__ ei) {
    __shared__ int cnt[N_NODES + 1];
    __shared__ int offs[N_NODES + 1];
    int tid = threadIdx.x;
    for (int i = tid; i <= N_NODES; i += blockDim.x) cnt[i] = 0;
    __syncthreads();
    for (int e = tid; e < N_EDGES; e += blockDim.x) {
        int dst = min(max(ei[N_EDGES + e], 0), N_NODES - 1);
        atomicAdd(&cnt[dst], 1);
    }
    __syncthreads();
    if (tid == 0) {
        int s = 0;
        for (int i = 0; i < N_NODES; i++) { offs[i] = s; s += cnt[i]; }
        offs[N_NODES] = s;
    }
    __syncthreads();
    for (int i = tid; i <= N_NODES; i += blockDim.x) { g_offs[i] = offs[i]; cnt[i] = offs[i]; }
    __syncthreads();
    for (int e = tid; e < N_EDGES; e += blockDim.x) {
        int src = min(max(ei[e], 0), N_NODES - 1);
        int dst = min(max(ei[N_EDGES + e], 0), N_NODES - 1);
        int pos = atomicAdd(&cnt[dst], 1);
        if (pos >= 0 && pos < N_EDGES) g_list[pos] = src;
    }
}

// ---------------- SAGE weight convert -> fp16 [672][672] ----------------------
__global__ void cw_sage(const float* __restrict__ wl, const float* __restrict__ wr) {
    int idx = blockIdx.x * blockDim.x + threadIdx.x;
    if (idx >= NPAD * (LKB / 4)) return;
    int nrow = idx / (LKB / 4);
    int k0   = (idx % (LKB / 4)) * 4;
    size_t off = (size_t)nrow * LKB + k0;
    float a[4], b[4];
#pragma unroll
    for (int e = 0; e < 4; e++) {
        int k = k0 + e;
        a[e] = (nrow < F_DIM && k < F_DIM) ? wl[(size_t)nrow * F_DIM + k] : 0.f;
        b[e] = (nrow < F_DIM && k < F_DIM) ? wr[(size_t)nrow * F_DIM + k] : 0.f;
    }
    *(uint2*)(g_wlh + off) = pack4h(a[0], a[1], a[2], a[3]);
    *(uint2*)(g_wrh + off) = pack4h(b[0], b[1], b[2], b[3]);
}

// ---------------- conv weight convert -> fp16 [256][CSROW] --------------------
__global__ void cw_conv(const float* __restrict__ cw) {
    int idx = blockIdx.x * blockDim.x + threadIdx.x;   // 256*80
    if (idx >= C_OUT * CK) return;
    int r = idx / CK, c = idx % CK;
    g_cwh[(size_t)r * CSROW + c] = __float2half_rn(cw[idx]);
}

// ---------------- im2col: x[116,64,657] -> g_im[4][116*768][CSROW] fp16 -------
__global__ void im2col(const float* __restrict__ x) {
    int idx = blockIdx.x * blockDim.x + threadIdx.x;   // g*116*768 + n*768 + t
    if (idx >= 4 * N_NODES * TPN) return;
    int g = idx / (N_NODES * TPN);
    int r = idx % (N_NODES * TPN);
    int n = r / TPN, t = r % TPN;
    __half hb[CK];
    if (t < F_DIM) {
#pragma unroll
        for (int ic = 0; ic < 16; ic++) {
            const float* xp = x + ((size_t)n * C_IN + g * 16 + ic) * T_IN + t;
#pragma unroll
            for (int k = 0; k < 5; k++) hb[ic * 5 + k] = __float2half_rn(xp[k]);
        }
    } else {
#pragma unroll
        for (int i = 0; i < CK; i++) hb[i] = __ushort_as_half(0);
    }
    uint4* dst = (uint4*)(g_im + (size_t)idx * CSROW);
    const uint4* srcv = (const uint4*)hb;
#pragma unroll
    for (int i = 0; i < 10; i++) dst[i] = srcv[i];
}

// ---------------- conv GEMM: C[128 t x 64 oc] = A@B^T -> hh0 (transposed) -----
__global__ void __launch_bounds__(256) conv_gemm(const float* __restrict__ cb) {
    const int tid = threadIdx.x;
    const int wid = tid >> 5;
    const int tt = blockIdx.x % 6;
    const int n  = blockIdx.x / 6;
    const int g  = blockIdx.y;

    const uint32_t sbase = smem_u32(dyn_smem);
    const __half* gA = g_im + ((size_t)(g * N_NODES + n) * TPN + tt * 128) * CSROW;
    const __half* gB = g_cwh + (size_t)g * 64 * CSROW;
    for (int i = tid; i < 1280; i += 256) {         // A: 128 rows x 10 chunks
        int row = i / 10, c = i % 10;
        cpa16(sbase + row * 176 + c * 16, gA + (size_t)row * CSROW + c * 8);
    }
    for (int i = tid; i < 640; i += 256) {          // B: 64 rows x 10 chunks
        int row = i / 10, c = i % 10;
        cpa16(sbase + 22528 + row * 176 + c * 16, gB + (size_t)row * CSROW + c * 8);
    }
    CP_COMMIT();
    CP_WAIT0();
    __syncthreads();

    const __half* sA = (const __half*)dyn_smem;
    const __half* sB = (const __half*)(dyn_smem + 22528);
    const int wm = (wid & 3) * 32;
    const int wn = (wid >> 2) * 32;

    wmma::fragment<wmma::accumulator, 16, 16, 16, float> acc[2][2];
#pragma unroll
    for (int i = 0; i < 2; i++)
#pragma unroll
        for (int j = 0; j < 2; j++) wmma::fill_fragment(acc[i][j], 0.f);

#pragma unroll
    for (int ks = 0; ks < 5; ks++) {
        wmma::fragment<wmma::matrix_a, 16, 16, 16, __half, wmma::row_major> af[2];
        wmma::fragment<wmma::matrix_b, 16, 16, 16, __half, wmma::col_major> bf[2];
#pragma unroll
        for (int i = 0; i < 2; i++)
            wmma::load_matrix_sync(af[i], sA + (wm + i * 16) * CSROW + ks * 16, CSROW);
#pragma unroll
        for (int j = 0; j < 2; j++)
            wmma::load_matrix_sync(bf[j], sB + (wn + j * 16) * CSROW + ks * 16, CSROW);
#pragma unroll
        for (int i = 0; i < 2; i++)
#pragma unroll
            for (int j = 0; j < 2; j++)
                wmma::mma_sync(acc[i][j], af[i], bf[j], acc[i][j]);
    }

    // store C transposed (col-major): Cs2[oc][t], ld = 132
    __syncthreads();
    float* Cs2 = (float*)dyn_smem;
#pragma unroll
    for (int i = 0; i < 2; i++)
#pragma unroll
        for (int j = 0; j < 2; j++)
            wmma::store_matrix_sync(Cs2 + (wm + i * 16) + (size_t)(wn + j * 16) * 132,
                                    acc[i][j], 132, wmma::mem_col_major);
    __syncthreads();

    // write hh0[(n*256 + g*64 + oc)*672 + t], bias + mask t>=653, zero pad
    const int lane = tid & 31;
#pragma unroll
    for (int it = 0; it < 8; it++) {
        int oc = (tid >> 5) + it * 8;
        int tg = tt * 128 + lane * 4;
        if (tg < NPAD) {
            float4 v = *(float4*)&Cs2[oc * 132 + lane * 4];
            float bias = cb[g * 64 + oc];
            float v0 = (tg + 0 < F_DIM) ? v.x + bias : 0.f;
            float v1 = (tg + 1 < F_DIM) ? v.y + bias : 0.f;
            float v2 = (tg + 2 < F_DIM) ? v.z + bias : 0.f;
            float v3 = (tg + 3 < F_DIM) ? v.w + bias : 0.f;
            *(uint2*)(g_hh0 + (size_t)(n * C_OUT + g * 64 + oc) * LKB + tg) =
                pack4h(v0, v1, v2, v3);
        }
    }
}

// ---------------- SAGE max-aggregation (fp16 in -> fp16 out) ------------------
__global__ void sage_agg(int src) {
    const __half* h = src ? g_hh1 : g_hh0;
    int row = blockIdx.x;          // n*256 + c
    int n = row >> 8;
    int c = row & 255;
    int beg = g_offs[n], end = g_offs[n + 1];
    size_t obase = (size_t)row * LKB;
    const __half2 NEG_INF2 = __halves2half2(__ushort_as_half(0xFC00u),
                                            __ushort_as_half(0xFC00u));
    for (int v = threadIdx.x; v < LKB / 4; v += blockDim.x) {
        int f0 = v * 4;
        uint2 outv = make_uint2(0u, 0u);
        if (end > beg) {
            __half2 m0 = NEG_INF2, m1 = NEG_INF2;
            for (int e = beg; e < end; e++) {
                int s = g_list[e];
                uint2 t = *(const uint2*)(h + ((size_t)s * C_OUT + c) * LKB + f0);
                m0 = __hmax2(m0, *(__half2*)&t.x);
                m1 = __hmax2(m1, *(__half2*)&t.y);
            }
            outv.x = *(uint32_t*)&m0;
            outv.y = *(uint32_t*)&m1;
        }
        *(uint2*)(g_aggh + obase + f0) = outv;
    }
}

// ---------------- WMMA fused SAGE GEMM ----------------------------------------
__device__ __forceinline__ void stage_copy(uint32_t sbase, int tid,
                                           const __half* pA, const __half* pB) {
#pragma unroll
    for (int t = 0; t < 4; t++) {
        int idx = tid + t * 256;
        if (idx < 512) {                    // A: 128 rows x 4 chunks
            int row = idx >> 2, c = idx & 3;
            cpa16(sbase + row * 112 + c * 16, pA + (size_t)row * LKB + c * 8);
        } else if (idx < 896) {             // B: 96 rows x 4 chunks
            int j = idx - 512;
            int row = j >> 2, c = j & 3;
            cpa16(sbase + A_B + row * 112 + c * 16, pB + (size_t)row * LKB + c * 8);
        }
    }
    CP_COMMIT();
}

__global__ void __launch_bounds__(256, 2) sage_gemm(int src,
                                                    const float* __restrict__ bias) {
    __shared__ float sbias[BN];
    const int tid = threadIdx.x;
    const int wid = tid >> 5;
    const int m0 = blockIdx.x * 128;
    const int n0 = blockIdx.y * BN;

    const __half* AArr[2] = { g_aggh, src ? g_hh1 : g_hh0 };
    const __half* BArr[2] = { g_wlh, g_wrh };
    __half* OutH = src ? g_hh0 : g_hh1;

    if (tid < BN) {
        int cg = n0 + tid;
        sbias[tid] = (cg < F_DIM) ? bias[cg] : 0.f;
    }

    const uint32_t smem_base = smem_u32(dyn_smem);

#pragma unroll
    for (int p = 0; p < 2; p++) {
        int k0 = p * BK;
        stage_copy(smem_base + p * STAGE_B, tid,
                   AArr[0] + (size_t)m0 * LKB + k0,
                   BArr[0] + (size_t)n0 * LKB + k0);
    }

    const int wm = (wid & 3) * 32;
    const int wn = (wid >> 2) * 48;

    wmma::fragment<wmma::accumulator, 16, 16, 16, float> acc[2][3];
#pragma unroll
    for (int i = 0; i < 2; i++)
#pragma unroll
        for (int j = 0; j < 3; j++) wmma::fill_fragment(acc[i][j], 0.f);

    for (int kt = 0; kt < KT_TOTAL; kt++) {
        CP_WAIT1();
        __syncthreads();
        const __half* sA = (const __half*)(dyn_smem + (kt & 1) * STAGE_B);
        const __half* sB = sA + OFF_Be;
#pragma unroll
        for (int ks = 0; ks < 2; ks++) {
            wmma::fragment<wmma::matrix_a, 16, 16, 16, __half, wmma::row_major> af[2];
            wmma::fragment<wmma::matrix_b, 16, 16, 16, __half, wmma::col_major> bf[3];
#pragma unroll
            for (int i = 0; i < 2; i++)
                wmma::load_matrix_sync(af[i], sA + (wm + i * 16) * SROW + ks * 16, SROW);
#pragma unroll
            for (int j = 0; j < 3; j++)
                wmma::load_matrix_sync(bf[j], sB + (wn + j * 16) * SROW + ks * 16, SROW);
#pragma unroll
            for (int i = 0; i < 2; i++)
#pragma unroll
                for (int j = 0; j < 3; j++)
                    wmma::mma_sync(acc[i][j], af[i], bf[j], acc[i][j]);
        }
        __syncthreads();
        int nk = kt + 2;
        if (nk < KT_TOTAL) {
            int ph = (nk >= KT_PHASE) ? 1 : 0;
            int k0 = (nk - ph * KT_PHASE) * BK;
            stage_copy(smem_base + (kt & 1) * STAGE_B, tid,
                       AArr[ph] + (size_t)m0 * LKB + k0,
                       BArr[ph] + (size_t)n0 * LKB + k0);
        } else {
            CP_COMMIT();
        }
    }

    __syncthreads();
    float* Cs = (float*)dyn_smem;       // [128][100]
#pragma unroll
    for (int i = 0; i < 2; i++)
#pragma unroll
        for (int j = 0; j < 3; j++)
            wmma::store_matrix_sync(&Cs[(wm + i * 16) * 100 + wn + j * 16], acc[i][j],
                                    100, wmma::mem_row_major);
    __syncthreads();

#pragma unroll
    for (int t = 0; t < 12; t++) {
        int q = tid + t * 256;          // 128 x 24 quads
        int row = q / 24;
        int col = (q % 24) * 4;
        float v0 = Cs[row * 100 + col + 0] + sbias[col + 0];
        float v1 = Cs[row * 100 + col + 1] + sbias[col + 1];
        float v2 = Cs[row * 100 + col + 2] + sbias[col + 2];
        float v3 = Cs[row * 100 + col + 3] + sbias[col + 3];
        int cg = n0 + col;
        int m = m0 + row;
        *(uint2*)(OutH + (size_t)m * LKB + cg) = pack4h(v0, v1, v2, v3);
    }
}

// ---------------- mean pool (fp16 in) -> g_mean fp32 ---------------------------
__global__ void mean_pool() {
    int idx = blockIdx.x * blockDim.x + threadIdx.x;
    if (idx >= C_OUT * LDF) return;
    int c = idx / LDF, f = idx % LDF;
    float s = 0.f;
    for (int n = 0; n < N_NODES; n++)
        s += __half2float(g_hh1[((size_t)n * C_OUT + c) * LKB + f]);
    g_mean[idx] = s * (1.f / N_NODES);
}

__device__ __forceinline__ float gelu_exact(float x) {
    return 0.5f * x * (1.f + erff(x * 0.70710678118654752f));
}

// ---------------- fc1 + gelu ----------------------------------------------------
__global__ void fc1_kernel(const float* __restrict__ w, const float* __restrict__ b) {
    __shared__ float row[F_DIM];
    int c = blockIdx.x;
    int tid = threadIdx.x;
    for (int f = tid; f < F_DIM; f += blockDim.x) row[f] = g_mean[c * LDF + f];
    __syncthreads();
    int warp = tid >> 5, lane = tid & 31;
    for (int g = warp; g < 128; g += blockDim.x / 32) {
        const float* wr = w + (size_t)g * F_DIM;
        float acc = 0.f;
        for (int f = lane; f < F_DIM; f += 32) acc = fmaf(row[f], wr[f], acc);
#pragma unroll
        for (int o = 16; o; o >>= 1) acc += __shfl_xor_sync(0xffffffffu, acc, o);
        if (lane == 0) g_fc1[c * 128 + g] = gelu_exact(acc + b[g]);
    }
}

// ---------------- fc2 + gelu + fc3 + softmax ------------------------------------
__global__ void head_kernel(const float* __restrict__ f2w, const float* __restrict__ f2b,
                            const float* __restrict__ f3w, const float* __restrict__ f3b,
                            float* __restrict__ out) {
    __shared__ float r1[128];
    __shared__ float r2[32];
    __shared__ float r3[4];
    int c = blockIdx.x;
    int tid = threadIdx.x;
    for (int i = tid; i < 128; i += 32) r1[i] = g_fc1[c * 128 + i];
    __syncthreads();
    {
        float acc = f2b[tid];
        const float* wr = f2w + (size_t)tid * 128;
        for (int f = 0; f < 128; f++) acc = fmaf(r1[f], wr[f], acc);
        r2[tid] = gelu_exact(acc);
    }
    __syncthreads();
    if (tid < 4) {
        float a = f3b[tid];
        const float* wr = f3w + (size_t)tid * 32;
        for (int f = 0; f < 32; f++) a = fmaf(r2[f], wr[f], a);
        r3[tid] = a;
    }
    __syncthreads();
    if (tid == 0) {
        float mx = fmaxf(fmaxf(r3[0], r3[1]), fmaxf(r3[2], r3[3]));
        float e0 = expf(r3[0] - mx), e1 = expf(r3[1] - mx);
        float e2 = expf(r3[2] - mx), e3 = expf(r3[3] - mx);
        float inv = 1.f / (e0 + e1 + e2 + e3);
        out[c * 4 + 0] = e0 * inv;
        out[c * 4 + 1] = e1 * inv;
        out[c * 4 + 2] = e2 * inv;
        out[c * 4 + 3] = e3 * inv;
    }
}

// ---------------- launch --------------------------------------------------------
extern "C" void kernel_launch(void* const* d_in, const int* in_sizes, int n_in,
                              void* d_out, int out_size) {
    const float* x      = (const float*)d_in[0];
    const int*   ei     = (const int*)d_in[1];
    const float* conv_w = (const float*)d_in[2];
    const float* conv_b = (const float*)d_in[3];
    const float* wl     = (const float*)d_in[4];
    const float* wr     = (const float*)d_in[5];
    const float* sb     = (const float*)d_in[6];
    const float* f1w    = (const float*)d_in[7];
    const float* f1b    = (const float*)d_in[8];
    const float* f2w    = (const float*)d_in[9];
    const float* f2b    = (const float*)d_in[10];
    const float* f3w    = (const float*)d_in[11];
    const float* f3b    = (const float*)d_in[12];
    float* out = (float*)d_out;

    cudaFuncSetAttribute(sage_gemm, cudaFuncAttributeMaxDynamicSharedMemorySize, GEMM_SMEM);

    build_csr<<<1, 128>>>(ei);
    cw_sage<<<(NPAD * (LKB / 4) + 255) / 256, 256>>>(wl, wr);
    cw_conv<<<(C_OUT * CK + 255) / 256, 256>>>(conv_w);
    im2col<<<(4 * N_NODES * TPN + 255) / 256, 256>>>(x);
    conv_gemm<<<dim3(N_NODES * 6, 4), 256, CGEMM_SMEM>>>(conv_b);

    // 3 SAGE layers (fp16 ping-pong hh0 <-> hh1); layer 2 ends in hh1.
    for (int l = 0; l < 3; l++) {
        int src = l & 1;
        sage_agg<<<M_ROWS, 128>>>(src);
        sage_gemm<<<dim3(M_TILES, N_TILES), 256, GEMM_SMEM>>>(src, sb);
    }

    mean_pool<<<(C_OUT * LDF + 255) / 256, 256>>>();
    fc1_kernel<<<256, 128>>>(f1w, f1b);
    head_kernel<<<256, 32>>>(f2w, f2b, f3w, f3b, out);
}

// round 13
// speedup vs baseline: 3.0090x; 1.0066x over previous
#include <cuda_runtime.h>
#include <cuda_fp16.h>
#include <mma.h>
#include <math.h>
#include <stdint.h>

using namespace nvcuda;

#define N_NODES 116
#define N_EDGES 1160
#define C_IN    64
#define T_IN    657
#define C_OUT   256
#define F_DIM   653
#define LDF     656
#define M_ROWS  (N_NODES * C_OUT)   // 29696
#define M_TILES 232                 // 29696/128
#define N_TILES 7                   // 7 * 96 = 672
#define BN      96
#define NPAD    672
#define LKB     672                 // fp16 row stride (padded K)
#define KT_PHASE 21                 // 672/32
#define KT_TOTAL 42

#define BK      32
#define SROW    56                  // padded smem row (fp16): 112B -> conflict-free LDSM
#define A_B     (128 * 112)         // 14336
#define B_B     (96 * 112)          // 10752
#define STAGE_B (A_B + B_B)         // 25088
#define GEMM_SMEM 51200             // max(2*STAGE_B=50176, epilogue 128*100*4)
#define OFF_Be  7168

// conv-as-GEMM constants (im2col fused in-kernel)
#define CK      80                  // conv K = 16 ic * 5 taps
#define CSROW   88                  // A/B smem row stride (fp16) = 176B, conflict-free
#define CA_B    22528               // A tile 128*176
#define CB_B    11264               // B tile 64*176
#define CX_OFF  (CA_B + CB_B)       // x staging after A,B: 33792
#define CX_B    (16 * 132 * 4)      // 8448
#define CGEMM_SMEM (CX_OFF + CX_B)  // 42240 (epilogue Cs2 = 64*132*4 = 33792 fits)

extern __shared__ __align__(128) unsigned char dyn_smem[];

// ---------------- device scratch --------------------------------------------
__device__ __align__(16) __half g_aggh[(size_t)M_ROWS * LKB];
__device__ __align__(16) __half g_hh0[(size_t)M_ROWS * LKB];
__device__ __align__(16) __half g_hh1[(size_t)M_ROWS * LKB];
__device__ __align__(16) __half g_wlh[(size_t)NPAD * LKB];
__device__ __align__(16) __half g_wrh[(size_t)NPAD * LKB];
__device__ __align__(16) __half g_cwh[(size_t)C_OUT * CSROW];
__device__ int   g_offs[N_NODES + 1];
__device__ int   g_list[N_EDGES];
__device__ float g_mean[C_OUT * LDF];
__device__ float g_fc1 [C_OUT * 128];

// ---------------- helpers -----------------------------------------------------
__device__ __forceinline__ uint32_t smem_u32(const void* p) {
    uint32_t a;
    asm("{ .reg .u64 t; cvta.to.shared.u64 t, %1; cvt.u32.u64 %0, t; }" : "=r"(a) : "l"(p));
    return a;
}
__device__ __forceinline__ void cpa16(uint32_t dst, const void* src) {
    asm volatile("cp.async.cg.shared.global [%0], [%1], 16;" :: "r"(dst), "l"(src));
}
#define CP_COMMIT() asm volatile("cp.async.commit_group;" ::: "memory")
#define CP_WAIT1()  asm volatile("cp.async.wait_group 1;" ::: "memory")
#define CP_WAIT0()  asm volatile("cp.async.wait_group 0;" ::: "memory")

__device__ __forceinline__ uint2 pack4h(float a, float b, float c, float d) {
    uint16_t ha = __half_as_ushort(__float2half_rn(a));
    uint16_t hb = __half_as_ushort(__float2half_rn(b));
    uint16_t hc = __half_as_ushort(__float2half_rn(c));
    uint16_t hd = __half_as_ushort(__float2half_rn(d));
    uint2 r;
    r.x = (uint32_t)ha | ((uint32_t)hb << 16);
    r.y = (uint32_t)hc | ((uint32_t)hd << 16);
    return r;
}

// ---------------- CSR build (edge_index arrives as int32) ---------------------
__global__ void build_csr(const int* __restrict__ ei) {
    __shared__ int cnt[N_NODES + 1];
    __shared__ int offs[N_NODES + 1];
    int tid = threadIdx.x;
    for (int i = tid; i <= N_NODES; i += blockDim.x) cnt[i] = 0;
    __syncthreads();
    for (int e = tid; e < N_EDGES; e += blockDim.x) {
        int dst = min(max(ei[N_EDGES + e], 0), N_NODES - 1);
        atomicAdd(&cnt[dst], 1);
    }
    __syncthreads();
    if (tid == 0) {
        int s = 0;
        for (int i = 0; i < N_NODES; i++) { offs[i] = s; s += cnt[i]; }
        offs[N_NODES] = s;
    }
    __syncthreads();
    for (int i = tid; i <= N_NODES; i += blockDim.x) { g_offs[i] = offs[i]; cnt[i] = offs[i]; }
    __syncthreads();
    for (int e = tid; e < N_EDGES; e += blockDim.x) {
        int src = min(max(ei[e], 0), N_NODES - 1);
        int dst = min(max(ei[N_EDGES + e], 0), N_NODES - 1);
        int pos = atomicAdd(&cnt[dst], 1);
        if (pos >= 0 && pos < N_EDGES) g_list[pos] = src;
    }
}

// ---------------- SAGE weight convert -> fp16 [672][672] ----------------------
__global__ void cw_sage(const float* __restrict__ wl, const float* __restrict__ wr) {
    int idx = blockIdx.x * blockDim.x + threadIdx.x;
    if (idx >= NPAD * (LKB / 4)) return;
    int nrow = idx / (LKB / 4);
    int k0   = (idx % (LKB / 4)) * 4;
    size_t off = (size_t)nrow * LKB + k0;
    float a[4], b[4];
#pragma unroll
    for (int e = 0; e < 4; e++) {
        int k = k0 + e;
        a[e] = (nrow < F_DIM && k < F_DIM) ? wl[(size_t)nrow * F_DIM + k] : 0.f;
        b[e] = (nrow < F_DIM && k < F_DIM) ? wr[(size_t)nrow * F_DIM + k] : 0.f;
    }
    *(uint2*)(g_wlh + off) = pack4h(a[0], a[1], a[2], a[3]);
    *(uint2*)(g_wrh + off) = pack4h(b[0], b[1], b[2], b[3]);
}

// ---------------- conv weight convert -> fp16 [256][CSROW] --------------------
__global__ void cw_conv(const float* __restrict__ cw) {
    int idx = blockIdx.x * blockDim.x + threadIdx.x;   // 256*80
    if (idx >= C_OUT * CK) return;
    int r = idx / CK, c = idx % CK;
    g_cwh[(size_t)r * CSROW + c] = __float2half_rn(cw[idx]);
}

// ---------------- conv GEMM with fused im2col ---------------------------------
// block (tt, n, g): C[128 t x 64 oc] = A@B^T, A built in-kernel from x.
__global__ void __launch_bounds__(256) conv_gemm(const float* __restrict__ x,
                                                 const float* __restrict__ cb) {
    const int tid = threadIdx.x;
    const int wid = tid >> 5;
    const int tt = blockIdx.x % 6;
    const int n  = blockIdx.x / 6;
    const int g  = blockIdx.y;

    const uint32_t sbase = smem_u32(dyn_smem);
    __half* sA = (__half*)dyn_smem;
    float*  xs = (float*)(dyn_smem + CX_OFF);      // [16][132]

    // async-load B (tiny, 64x80 fp16)
    const __half* gB = g_cwh + (size_t)g * 64 * CSROW;
    for (int i = tid; i < 640; i += 256) {
        int row = i / 10, c = i % 10;
        cpa16(sbase + CA_B + row * 176 + c * 16, gB + (size_t)row * CSROW + c * 8);
    }
    CP_COMMIT();

    // load x slice [16 ic][132 t] fp32 into smem (coalesced over t)
    {
        const float* xb = x + ((size_t)n * C_IN + g * 16) * T_IN;
        int t0 = tt * 128;
        for (int i = tid; i < 16 * 132; i += 256) {
            int ic = i / 132, o = i % 132;
            int t = t0 + o;
            xs[ic * 132 + o] = (t < T_IN) ? xb[(size_t)ic * T_IN + t] : 0.f;
        }
    }
    __syncthreads();

    // build A[128 rows][80 cols] fp16: A[row][ic*5+k] = xs[ic][row+k]
    for (int p = tid; p < 128 * 40; p += 256) {
        int row = p / 40, cp = p % 40;
        int c0 = cp * 2, c1 = c0 + 1;
        float e0 = xs[(c0 / 5) * 132 + row + (c0 % 5)];
        float e1 = xs[(c1 / 5) * 132 + row + (c1 % 5)];
        __half2 h2 = __floats2half2_rn(e0, e1);
        *(uint32_t*)((char*)sA + row * 176 + cp * 4) = *(uint32_t*)&h2;
    }
    CP_WAIT0();
    __syncthreads();

    const __half* sB = (const __half*)(dyn_smem + CA_B);
    const int wm = (wid & 3) * 32;
    const int wn = (wid >> 2) * 32;

    wmma::fragment<wmma::accumulator, 16, 16, 16, float> acc[2][2];
#pragma unroll
    for (int i = 0; i < 2; i++)
#pragma unroll
        for (int j = 0; j < 2; j++) wmma::fill_fragment(acc[i][j], 0.f);

#pragma unroll
    for (int ks = 0; ks < 5; ks++) {
        wmma::fragment<wmma::matrix_a, 16, 16, 16, __half, wmma::row_major> af[2];
        wmma::fragment<wmma::matrix_b, 16, 16, 16, __half, wmma::col_major> bf[2];
#pragma unroll
        for (int i = 0; i < 2; i++)
            wmma::load_matrix_sync(af[i], sA + (wm + i * 16) * CSROW + ks * 16, CSROW);
#pragma unroll
        for (int j = 0; j < 2; j++)
            wmma::load_matrix_sync(bf[j], sB + (wn + j * 16) * CSROW + ks * 16, CSROW);
#pragma unroll
        for (int i = 0; i < 2; i++)
#pragma unroll
            for (int j = 0; j < 2; j++)
                wmma::mma_sync(acc[i][j], af[i], bf[j], acc[i][j]);
    }

    // store C transposed (col-major): Cs2[oc][t], ld = 132
    __syncthreads();
    float* Cs2 = (float*)dyn_smem;
#pragma unroll
    for (int i = 0; i < 2; i++)
#pragma unroll
        for (int j = 0; j < 2; j++)
            wmma::store_matrix_sync(Cs2 + (wm + i * 16) + (size_t)(wn + j * 16) * 132,
                                    acc[i][j], 132, wmma::mem_col_major);
    __syncthreads();

    // write hh0[(n*256 + g*64 + oc)*672 + t], bias + mask t>=653
    const int lane = tid & 31;
#pragma unroll
    for (int it = 0; it < 8; it++) {
        int oc = (tid >> 5) + it * 8;
        int tg = tt * 128 + lane * 4;
        if (tg < NPAD) {
            float4 v = *(float4*)&Cs2[oc * 132 + lane * 4];
            float bias = cb[g * 64 + oc];
            float v0 = (tg + 0 < F_DIM) ? v.x + bias : 0.f;
            float v1 = (tg + 1 < F_DIM) ? v.y + bias : 0.f;
            float v2 = (tg + 2 < F_DIM) ? v.z + bias : 0.f;
            float v3 = (tg + 3 < F_DIM) ? v.w + bias : 0.f;
            *(uint2*)(g_hh0 + (size_t)(n * C_OUT + g * 64 + oc) * LKB + tg) =
                pack4h(v0, v1, v2, v3);
        }
    }
}

// ---------------- SAGE max-aggregation (fp16 in -> fp16 out) ------------------
__global__ void sage_agg(int src) {
    const __half* h = src ? g_hh1 : g_hh0;
    int row = blockIdx.x;          // n*256 + c
    int n = row >> 8;
    int c = row & 255;
    int beg = g_offs[n], end = g_offs[n + 1];
    size_t obase = (size_t)row * LKB;
    const __half2 NEG_INF2 = __halves2half2(__ushort_as_half(0xFC00u),
                                            __ushort_as_half(0xFC00u));
    for (int v = threadIdx.x; v < LKB / 4; v += blockDim.x) {
        int f0 = v * 4;
        uint2 outv = make_uint2(0u, 0u);
        if (end > beg) {
            __half2 m0 = NEG_INF2, m1 = NEG_INF2;
            for (int e = beg; e < end; e++) {
                int s = g_list[e];
                uint2 t = *(const uint2*)(h + ((size_t)s * C_OUT + c) * LKB + f0);
                m0 = __hmax2(m0, *(__half2*)&t.x);
                m1 = __hmax2(m1, *(__half2*)&t.y);
            }
            outv.x = *(uint32_t*)&m0;
            outv.y = *(uint32_t*)&m1;
        }
        *(uint2*)(g_aggh + obase + f0) = outv;
    }
}

// ---------------- WMMA fused SAGE GEMM ----------------------------------------
__device__ __forceinline__ void stage_copy(uint32_t sbase, int tid,
                                           const __half* pA, const __half* pB) {
#pragma unroll
    for (int t = 0; t < 4; t++) {
        int idx = tid + t * 256;
        if (idx < 512) {                    // A: 128 rows x 4 chunks
            int row = idx >> 2, c = idx & 3;
            cpa16(sbase + row * 112 + c * 16, pA + (size_t)row * LKB + c * 8);
        } else if (idx < 896) {             // B: 96 rows x 4 chunks
            int j = idx - 512;
            int row = j >> 2, c = j & 3;
            cpa16(sbase + A_B + row * 112 + c * 16, pB + (size_t)row * LKB + c * 8);
        }
    }
    CP_COMMIT();
}

__global__ void __launch_bounds__(256, 2) sage_gemm(int src,
                                                    const float* __restrict__ bias) {
    __shared__ float sbias[BN];
    const int tid = threadIdx.x;
    const int wid = tid >> 5;
    const int m0 = blockIdx.x * 128;
    const int n0 = blockIdx.y * BN;

    const __half* AArr[2] = { g_aggh, src ? g_hh1 : g_hh0 };
    const __half* BArr[2] = { g_wlh, g_wrh };
    __half* OutH = src ? g_hh0 : g_hh1;

    if (tid < BN) {
        int cg = n0 + tid;
        sbias[tid] = (cg < F_DIM) ? bias[cg] : 0.f;
    }

    const uint32_t smem_base = smem_u32(dyn_smem);

#pragma unroll
    for (int p = 0; p < 2; p++) {
        int k0 = p * BK;
        stage_copy(smem_base + p * STAGE_B, tid,
                   AArr[0] + (size_t)m0 * LKB + k0,
                   BArr[0] + (size_t)n0 * LKB + k0);
    }

    const int wm = (wid & 3) * 32;
    const int wn = (wid >> 2) * 48;

    wmma::fragment<wmma::accumulator, 16, 16, 16, float> acc[2][3];
#pragma unroll
    for (int i = 0; i < 2; i++)
#pragma unroll
        for (int j = 0; j < 3; j++) wmma::fill_fragment(acc[i][j], 0.f);

    for (int kt = 0; kt < KT_TOTAL; kt++) {
        CP_WAIT1();
        __syncthreads();
        const __half* sA = (const __half*)(dyn_smem + (kt & 1) * STAGE_B);
        const __half* sB = sA + OFF_Be;
#pragma unroll
        for (int ks = 0; ks < 2; ks++) {
            wmma::fragment<wmma::matrix_a, 16, 16, 16, __half, wmma::row_major> af[2];
            wmma::fragment<wmma::matrix_b, 16, 16, 16, __half, wmma::col_major> bf[3];
#pragma unroll
            for (int i = 0; i < 2; i++)
                wmma::load_matrix_sync(af[i], sA + (wm + i * 16) * SROW + ks * 16, SROW);
#pragma unroll
            for (int j = 0; j < 3; j++)
                wmma::load_matrix_sync(bf[j], sB + (wn + j * 16) * SROW + ks * 16, SROW);
#pragma unroll
            for (int i = 0; i < 2; i++)
#pragma unroll
                for (int j = 0; j < 3; j++)
                    wmma::mma_sync(acc[i][j], af[i], bf[j], acc[i][j]);
        }
        __syncthreads();
        int nk = kt + 2;
        if (nk < KT_TOTAL) {
            int ph = (nk >= KT_PHASE) ? 1 : 0;
            int k0 = (nk - ph * KT_PHASE) * BK;
            stage_copy(smem_base + (kt & 1) * STAGE_B, tid,
                       AArr[ph] + (size_t)m0 * LKB + k0,
                       BArr[ph] + (size_t)n0 * LKB + k0);
        } else {
            CP_COMMIT();
        }
    }

    __syncthreads();
    float* Cs = (float*)dyn_smem;       // [128][100]
#pragma unroll
    for (int i = 0; i < 2; i++)
#pragma unroll
        for (int j = 0; j < 3; j++)
            wmma::store_matrix_sync(&Cs[(wm + i * 16) * 100 + wn + j * 16], acc[i][j],
                                    100, wmma::mem_row_major);
    __syncthreads();

#pragma unroll
    for (int t = 0; t < 12; t++) {
        int q = tid + t * 256;          // 128 x 24 quads
        int row = q / 24;
        int col = (q % 24) * 4;
        float v0 = Cs[row * 100 + col + 0] + sbias[col + 0];
        float v1 = Cs[row * 100 + col + 1] + sbias[col + 1];
        float v2 = Cs[row * 100 + col + 2] + sbias[col + 2];
        float v3 = Cs[row * 100 + col + 3] + sbias[col + 3];
        int cg = n0 + col;
        int m = m0 + row;
        *(uint2*)(OutH + (size_t)m * LKB + cg) = pack4h(v0, v1, v2, v3);
    }
}

// ---------------- mean pool (fp16 in) -> g_mean fp32 ---------------------------
__global__ void mean_pool() {
    int idx = blockIdx.x * blockDim.x + threadIdx.x;
    if (idx >= C_OUT * LDF) return;
    int c = idx / LDF, f = idx % LDF;
    float s = 0.f;
    for (int n = 0; n < N_NODES; n++)
        s += __half2float(g_hh1[((size_t)n * C_OUT + c) * LKB + f]);
    g_mean[idx] = s * (1.f / N_NODES);
}

__device__ __forceinline__ float gelu_exact(float x) {
    return 0.5f * x * (1.f + erff(x * 0.70710678118654752f));
}

// ---------------- fc1 + gelu ----------------------------------------------------
__global__ void fc1_kernel(const float* __restrict__ w, const float* __restrict__ b) {
    __shared__ float row[F_DIM];
    int c = blockIdx.x;
    int tid = threadIdx.x;
    for (int f = tid; f < F_DIM; f += blockDim.x) row[f] = g_mean[c * LDF + f];
    __syncthreads();
    int warp = tid >> 5, lane = tid & 31;
    for (int g = warp; g < 128; g += blockDim.x / 32) {
        const float* wr = w + (size_t)g * F_DIM;
        float acc = 0.f;
        for (int f = lane; f < F_DIM; f += 32) acc = fmaf(row[f], wr[f], acc);
#pragma unroll
        for (int o = 16; o; o >>= 1) acc += __shfl_xor_sync(0xffffffffu, acc, o);
        if (lane == 0) g_fc1[c * 128 + g] = gelu_exact(acc + b[g]);
    }
}

// ---------------- fc2 + gelu + fc3 + softmax ------------------------------------
__global__ void head_kernel(const float* __restrict__ f2w, const float* __restrict__ f2b,
                            const float* __restrict__ f3w, const float* __restrict__ f3b,
                            float* __restrict__ out) {
    __shared__ float r1[128];
    __shared__ float r2[32];
    __shared__ float r3[4];
    int c = blockIdx.x;
    int tid = threadIdx.x;
    for (int i = tid; i < 128; i += 32) r1[i] = g_fc1[c * 128 + i];
    __syncthreads();
    {
        float acc = f2b[tid];
        const float* wr = f2w + (size_t)tid * 128;
        for (int f = 0; f < 128; f++) acc = fmaf(r1[f], wr[f], acc);
        r2[tid] = gelu_exact(acc);
    }
    __syncthreads();
    if (tid < 4) {
        float a = f3b[tid];
        const float* wr = f3w + (size_t)tid * 32;
        for (int f = 0; f < 32; f++) a = fmaf(r2[f], wr[f], a);
        r3[tid] = a;
    }
    __syncthreads();
    if (tid == 0) {
        float mx = fmaxf(fmaxf(r3[0], r3[1]), fmaxf(r3[2], r3[3]));
        float e0 = expf(r3[0] - mx), e1 = expf(r3[1] - mx);
        float e2 = expf(r3[2] - mx), e3 = expf(r3[3] - mx);
        float inv = 1.f / (e0 + e1 + e2 + e3);
        out[c * 4 + 0] = e0 * inv;
        out[c * 4 + 1] = e1 * inv;
        out[c * 4 + 2] = e2 * inv;
        out[c * 4 + 3] = e3 * inv;
    }
}

// ---------------- launch --------------------------------------------------------
extern "C" void kernel_launch(void* const* d_in, const int* in_sizes, int n_in,
                              void* d_out, int out_size) {
    const float* x      = (const float*)d_in[0];
    const int*   ei     = (const int*)d_in[1];
    const float* conv_w = (const float*)d_in[2];
    const float* conv_b = (const float*)d_in[3];
    const float* wl     = (const float*)d_in[4];
    const float* wr     = (const float*)d_in[5];
    const float* sb     = (const float*)d_in[6];
    const float* f1w    = (const float*)d_in[7];
    const float* f1b    = (const float*)d_in[8];
    const float* f2w    = (const float*)d_in[9];
    const float* f2b    = (const float*)d_in[10];
    const float* f3w    = (const float*)d_in[11];
    const float* f3b    = (const float*)d_in[12];
    float* out = (float*)d_out;

    cudaFuncSetAttribute(sage_gemm, cudaFuncAttributeMaxDynamicSharedMemorySize, GEMM_SMEM);

    build_csr<<<1, 128>>>(ei);
    cw_sage<<<(NPAD * (LKB / 4) + 255) / 256, 256>>>(wl, wr);
    cw_conv<<<(C_OUT * CK + 255) / 256, 256>>>(conv_w);
    conv_gemm<<<dim3(N_NODES * 6, 4), 256, CGEMM_SMEM>>>(x, conv_b);

    // 3 SAGE layers (fp16 ping-pong hh0 <-> hh1); layer 2 ends in hh1.
    for (int l = 0; l < 3; l++) {
        int src = l & 1;
        sage_agg<<<M_ROWS, 128>>>(src);
        sage_gemm<<<dim3(M_TILES, N_TILES), 256, GEMM_SMEM>>>(src, sb);
    }

    mean_pool<<<(C_OUT * LDF + 255) / 256, 256>>>();
    fc1_kernel<<<256, 128>>>(f1w, f1b);
    head_kernel<<<256, 32>>>(f2w, f2b, f3w, f3b, out);
}

// round 14
// speedup vs baseline: 3.3046x; 1.0982x over previous
#include <cuda_runtime.h>
#include <cuda_fp16.h>
#include <mma.h>
#include <math.h>
#include <stdint.h>

using namespace nvcuda;

#define N_NODES 116
#define N_EDGES 1160
#define C_IN    64
#define T_IN    657
#define C_OUT   256
#define F_DIM   653
#define LDF     656
#define M_ROWS  (N_NODES * C_OUT)   // 29696
#define M_TILES 232                 // 29696/128
#define N_TILES 7                   // 7 * 96 = 672
#define BN      96
#define NPAD    672
#define LKB     672                 // fp16 row stride (padded K)
#define KT_PHASE 21                 // 672/32
#define KT_TOTAL 42

#define BK      32
#define SROW    56                  // padded smem row (fp16): 112B -> conflict-free LDSM
#define A_B     (128 * 112)         // 14336
#define B_B     (96 * 112)          // 10752
#define STAGE_B (A_B + B_B)         // 25088
#define STAGES  3
#define GEMM_SMEM (STAGES * STAGE_B)   // 75264 (epilogue 128*100*4 = 51200 fits)
#define OFF_Be  7168

// conv-as-GEMM constants (im2col fused in-kernel)
#define CK      80                  // conv K = 16 ic * 5 taps
#define CSROW   88                  // A/B smem row stride (fp16) = 176B, conflict-free
#define CA_B    22528               // A tile 128*176
#define CB_B    11264               // B tile 64*176
#define CX_OFF  (CA_B + CB_B)       // x staging after A,B: 33792
#define CX_B    (16 * 132 * 4)      // 8448
#define CGEMM_SMEM (CX_OFF + CX_B)  // 42240 (epilogue Cs2 = 64*132*4 = 33792 fits)

extern __shared__ __align__(128) unsigned char dyn_smem[];

// ---------------- device scratch --------------------------------------------
__device__ __align__(16) __half g_aggh[(size_t)M_ROWS * LKB];
__device__ __align__(16) __half g_hh0[(size_t)M_ROWS * LKB];
__device__ __align__(16) __half g_hh1[(size_t)M_ROWS * LKB];
__device__ __align__(16) __half g_wlh[(size_t)NPAD * LKB];
__device__ __align__(16) __half g_wrh[(size_t)NPAD * LKB];
__device__ __align__(16) __half g_cwh[(size_t)C_OUT * CSROW];
__device__ int   g_offs[N_NODES + 1];
__device__ int   g_list[N_EDGES];
__device__ float g_mean[C_OUT * LDF];
__device__ float g_fc1 [C_OUT * 128];

// ---------------- helpers -----------------------------------------------------
__device__ __forceinline__ uint32_t smem_u32(const void* p) {
    uint32_t a;
    asm("{ .reg .u64 t; cvta.to.shared.u64 t, %1; cvt.u32.u64 %0, t; }" : "=r"(a) : "l"(p));
    return a;
}
__device__ __forceinline__ void cpa16(uint32_t dst, const void* src) {
    asm volatile("cp.async.cg.shared.global [%0], [%1], 16;" :: "r"(dst), "l"(src));
}
#define CP_COMMIT() asm volatile("cp.async.commit_group;" ::: "memory")
#define CP_WAIT1()  asm volatile("cp.async.wait_group 1;" ::: "memory")
#define CP_WAIT0()  asm volatile("cp.async.wait_group 0;" ::: "memory")

__device__ __forceinline__ uint2 pack4h(float a, float b, float c, float d) {
    uint16_t ha = __half_as_ushort(__float2half_rn(a));
    uint16_t hb = __half_as_ushort(__float2half_rn(b));
    uint16_t hc = __half_as_ushort(__float2half_rn(c));
    uint16_t hd = __half_as_ushort(__float2half_rn(d));
    uint2 r;
    r.x = (uint32_t)ha | ((uint32_t)hb << 16);
    r.y = (uint32_t)hc | ((uint32_t)hd << 16);
    return r;
}

// ---------------- CSR build (edge_index arrives as int32) ---------------------
__global__ void build_csr(const int* __restrict__ ei) {
    __shared__ int cnt[N_NODES + 1];
    __shared__ int offs[N_NODES + 1];
    int tid = threadIdx.x;
    for (int i = tid; i <= N_NODES; i += blockDim.x) cnt[i] = 0;
    __syncthreads();
    for (int e = tid; e < N_EDGES; e += blockDim.x) {
        int dst = min(max(ei[N_EDGES + e], 0), N_NODES - 1);
        atomicAdd(&cnt[dst], 1);
    }
    __syncthreads();
    if (tid == 0) {
        int s = 0;
        for (int i = 0; i < N_NODES; i++) { offs[i] = s; s += cnt[i]; }
        offs[N_NODES] = s;
    }
    __syncthreads();
    for (int i = tid; i <= N_NODES; i += blockDim.x) { g_offs[i] = offs[i]; cnt[i] = offs[i]; }
    __syncthreads();
    for (int e = tid; e < N_EDGES; e += blockDim.x) {
        int src = min(max(ei[e], 0), N_NODES - 1);
        int dst = min(max(ei[N_EDGES + e], 0), N_NODES - 1);
        int pos = atomicAdd(&cnt[dst], 1);
        if (pos >= 0 && pos < N_EDGES) g_list[pos] = src;
    }
}

// ---------------- SAGE weight convert -> fp16 [672][672] ----------------------
__global__ void cw_sage(const float* __restrict__ wl, const float* __restrict__ wr) {
    int idx = blockIdx.x * blockDim.x + threadIdx.x;
    if (idx >= NPAD * (LKB / 4)) return;
    int nrow = idx / (LKB / 4);
    int k0   = (idx % (LKB / 4)) * 4;
    size_t off = (size_t)nrow * LKB + k0;
    float a[4], b[4];
#pragma unroll
    for (int e = 0; e < 4; e++) {
        int k = k0 + e;
        a[e] = (nrow < F_DIM && k < F_DIM) ? wl[(size_t)nrow * F_DIM + k] : 0.f;
        b[e] = (nrow < F_DIM && k < F_DIM) ? wr[(size_t)nrow * F_DIM + k] : 0.f;
    }
    *(uint2*)(g_wlh + off) = pack4h(a[0], a[1], a[2], a[3]);
    *(uint2*)(g_wrh + off) = pack4h(b[0], b[1], b[2], b[3]);
}

// ---------------- conv weight convert -> fp16 [256][CSROW] --------------------
__global__ void cw_conv(const float* __restrict__ cw) {
    int idx = blockIdx.x * blockDim.x + threadIdx.x;   // 256*80
    if (idx >= C_OUT * CK) return;
    int r = idx / CK, c = idx % CK;
    g_cwh[(size_t)r * CSROW + c] = __float2half_rn(cw[idx]);
}

// ---------------- conv GEMM with fused im2col ---------------------------------
// block (tt, n, g): C[128 t x 64 oc] = A@B^T, A built in-kernel from x.
__global__ void __launch_bounds__(256) conv_gemm(const float* __restrict__ x,
                                                 const float* __restrict__ cb) {
    const int tid = threadIdx.x;
    const int wid = tid >> 5;
    const int tt = blockIdx.x % 6;
    const int n  = blockIdx.x / 6;
    const int g  = blockIdx.y;

    const uint32_t sbase = smem_u32(dyn_smem);
    __half* sA = (__half*)dyn_smem;
    float*  xs = (float*)(dyn_smem + CX_OFF);      // [16][132]

    // async-load B (tiny, 64x80 fp16)
    const __half* gB = g_cwh + (size_t)g * 64 * CSROW;
    for (int i = tid; i < 640; i += 256) {
        int row = i / 10, c = i % 10;
        cpa16(sbase + CA_B + row * 176 + c * 16, gB + (size_t)row * CSROW + c * 8);
    }
    CP_COMMIT();

    // load x slice [16 ic][132 t] fp32 into smem (coalesced over t)
    {
        const float* xb = x + ((size_t)n * C_IN + g * 16) * T_IN;
        int t0 = tt * 128;
        for (int i = tid; i < 16 * 132; i += 256) {
            int ic = i / 132, o = i % 132;
            int t = t0 + o;
            xs[ic * 132 + o] = (t < T_IN) ? xb[(size_t)ic * T_IN + t] : 0.f;
        }
    }
    __syncthreads();

    // build A[128 rows][80 cols] fp16: A[row][ic*5+k] = xs[ic][row+k]
    // 2 threads per row; fully unrolled so ic = c/5, k = c%5 constant-fold.
    {
        int row = tid >> 1;
        char* dstrow = (char*)sA + row * 176;
        const float* xrow = xs + row;
        if ((tid & 1) == 0) {
#pragma unroll
            for (int cp = 0; cp < 20; cp++) {
                const int c0 = cp * 2, c1 = c0 + 1;
                float e0 = xrow[(c0 / 5) * 132 + (c0 % 5)];
                float e1 = xrow[(c1 / 5) * 132 + (c1 % 5)];
                __half2 h2 = __floats2half2_rn(e0, e1);
                *(uint32_t*)(dstrow + cp * 4) = *(uint32_t*)&h2;
            }
        } else {
#pragma unroll
            for (int cp = 20; cp < 40; cp++) {
                const int c0 = cp * 2, c1 = c0 + 1;
                float e0 = xrow[(c0 / 5) * 132 + (c0 % 5)];
                float e1 = xrow[(c1 / 5) * 132 + (c1 % 5)];
                __half2 h2 = __floats2half2_rn(e0, e1);
                *(uint32_t*)(dstrow + cp * 4) = *(uint32_t*)&h2;
            }
        }
    }
    CP_WAIT0();
    __syncthreads();

    const __half* sB = (const __half*)(dyn_smem + CA_B);
    const int wm = (wid & 3) * 32;
    const int wn = (wid >> 2) * 32;

    wmma::fragment<wmma::accumulator, 16, 16, 16, float> acc[2][2];
#pragma unroll
    for (int i = 0; i < 2; i++)
#pragma unroll
        for (int j = 0; j < 2; j++) wmma::fill_fragment(acc[i][j], 0.f);

#pragma unroll
    for (int ks = 0; ks < 5; ks++) {
        wmma::fragment<wmma::matrix_a, 16, 16, 16, __half, wmma::row_major> af[2];
        wmma::fragment<wmma::matrix_b, 16, 16, 16, __half, wmma::col_major> bf[2];
#pragma unroll
        for (int i = 0; i < 2; i++)
            wmma::load_matrix_sync(af[i], sA + (wm + i * 16) * CSROW + ks * 16, CSROW);
#pragma unroll
        for (int j = 0; j < 2; j++)
            wmma::load_matrix_sync(bf[j], sB + (wn + j * 16) * CSROW + ks * 16, CSROW);
#pragma unroll
        for (int i = 0; i < 2; i++)
#pragma unroll
            for (int j = 0; j < 2; j++)
                wmma::mma_sync(acc[i][j], af[i], bf[j], acc[i][j]);
    }

    // store C transposed (col-major): Cs2[oc][t], ld = 132
    __syncthreads();
    float* Cs2 = (float*)dyn_smem;
#pragma unroll
    for (int i = 0; i < 2; i++)
#pragma unroll
        for (int j = 0; j < 2; j++)
            wmma::store_matrix_sync(Cs2 + (wm + i * 16) + (size_t)(wn + j * 16) * 132,
                                    acc[i][j], 132, wmma::mem_col_major);
    __syncthreads();

    // write hh0[(n*256 + g*64 + oc)*672 + t], bias + mask t>=653
    const int lane = tid & 31;
#pragma unroll
    for (int it = 0; it < 8; it++) {
        int oc = (tid >> 5) + it * 8;
        int tg = tt * 128 + lane * 4;
        if (tg < NPAD) {
            float4 v = *(float4*)&Cs2[oc * 132 + lane * 4];
            float bias = cb[g * 64 + oc];
            float v0 = (tg + 0 < F_DIM) ? v.x + bias : 0.f;
            float v1 = (tg + 1 < F_DIM) ? v.y + bias : 0.f;
            float v2 = (tg + 2 < F_DIM) ? v.z + bias : 0.f;
            float v3 = (tg + 3 < F_DIM) ? v.w + bias : 0.f;
            *(uint2*)(g_hh0 + (size_t)(n * C_OUT + g * 64 + oc) * LKB + tg) =
                pack4h(v0, v1, v2, v3);
        }
    }
}

// ---------------- SAGE max-aggregation (fp16 in -> fp16 out) ------------------
__global__ void sage_agg(int src) {
    const __half* h = src ? g_hh1 : g_hh0;
    int row = blockIdx.x;          // n*256 + c
    int n = row >> 8;
    int c = row & 255;
    int beg = g_offs[n], end = g_offs[n + 1];
    size_t obase = (size_t)row * LKB;
    const __half2 NEG_INF2 = __halves2half2(__ushort_as_half(0xFC00u),
                                            __ushort_as_half(0xFC00u));
    for (int v = threadIdx.x; v < LKB / 4; v += blockDim.x) {
        int f0 = v * 4;
        uint2 outv = make_uint2(0u, 0u);
        if (end > beg) {
            __half2 m0 = NEG_INF2, m1 = NEG_INF2;
            for (int e = beg; e < end; e++) {
                int s = g_list[e];
                uint2 t = *(const uint2*)(h + ((size_t)s * C_OUT + c) * LKB + f0);
                m0 = __hmax2(m0, *(__half2*)&t.x);
                m1 = __hmax2(m1, *(__half2*)&t.y);
            }
            outv.x = *(uint32_t*)&m0;
            outv.y = *(uint32_t*)&m1;
        }
        *(uint2*)(g_aggh + obase + f0) = outv;
    }
}

// ---------------- WMMA fused SAGE GEMM ----------------------------------------
// 3-stage cp.async pipeline, ONE barrier per k-iteration (BK=32 ILP kept).
__device__ __forceinline__ void stage_copy(uint32_t sbase, int tid,
                                           const __half* pA, const __half* pB) {
#pragma unroll
    for (int t = 0; t < 4; t++) {
        int idx = tid + t * 256;
        if (idx < 512) {                    // A: 128 rows x 4 chunks
            int row = idx >> 2, c = idx & 3;
            cpa16(sbase + row * 112 + c * 16, pA + (size_t)row * LKB + c * 8);
        } else if (idx < 896) {             // B: 96 rows x 4 chunks
            int j = idx - 512;
            int row = j >> 2, c = j & 3;
            cpa16(sbase + A_B + row * 112 + c * 16, pB + (size_t)row * LKB + c * 8);
        }
    }
    CP_COMMIT();
}

__global__ void __launch_bounds__(256, 2) sage_gemm(int src,
                                                    const float* __restrict__ bias) {
    __shared__ float sbias[BN];
    const int tid = threadIdx.x;
    const int wid = tid >> 5;
    const int m0 = blockIdx.x * 128;
    const int n0 = blockIdx.y * BN;

    const __half* AArr[2] = { g_aggh, src ? g_hh1 : g_hh0 };
    const __half* BArr[2] = { g_wlh, g_wrh };
    __half* OutH = src ? g_hh0 : g_hh1;

    if (tid < BN) {
        int cg = n0 + tid;
        sbias[tid] = (cg < F_DIM) ? bias[cg] : 0.f;
    }

    const uint32_t smem_base = smem_u32(dyn_smem);

    // prologue: stages 0,1 (both phase 0 since KT_PHASE=21 > 1)
#pragma unroll
    for (int p = 0; p < 2; p++) {
        int k0 = p * BK;
        stage_copy(smem_base + p * STAGE_B, tid,
                   AArr[0] + (size_t)m0 * LKB + k0,
                   BArr[0] + (size_t)n0 * LKB + k0);
    }

    const int wm = (wid & 3) * 32;
    const int wn = (wid >> 2) * 48;

    wmma::fragment<wmma::accumulator, 16, 16, 16, float> acc[2][3];
#pragma unroll
    for (int i = 0; i < 2; i++)
#pragma unroll
        for (int j = 0; j < 3; j++) wmma::fill_fragment(acc[i][j], 0.f);

    int buf = 0;                    // stage kt lives in buffer kt % 3
    for (int kt = 0; kt < KT_TOTAL; kt++) {
        CP_WAIT1();                 // allow 1 outstanding group -> stage kt landed
        __syncthreads();            // all warps done computing kt-1 (its buffer is free)
        int nk = kt + 2;
        if (nk < KT_TOTAL) {        // issue into buffer (kt+2)%3 == (kt-1)%3
            int ph = (nk >= KT_PHASE) ? 1 : 0;
            int k0 = (nk - ph * KT_PHASE) * BK;
            int nbuf = buf + 2; if (nbuf >= 3) nbuf -= 3;
            stage_copy(smem_base + nbuf * STAGE_B, tid,
                       AArr[ph] + (size_t)m0 * LKB + k0,
                       BArr[ph] + (size_t)n0 * LKB + k0);
        } else {
            CP_COMMIT();            // keep group counting consistent
        }
        const __half* sA = (const __half*)(dyn_smem + buf * STAGE_B);
        const __half* sB = sA + OFF_Be;
#pragma unroll
        for (int ks = 0; ks < 2; ks++) {
            wmma::fragment<wmma::matrix_a, 16, 16, 16, __half, wmma::row_major> af[2];
            wmma::fragment<wmma::matrix_b, 16, 16, 16, __half, wmma::col_major> bf[3];
#pragma unroll
            for (int i = 0; i < 2; i++)
                wmma::load_matrix_sync(af[i], sA + (wm + i * 16) * SROW + ks * 16, SROW);
#pragma unroll
            for (int j = 0; j < 3; j++)
                wmma::load_matrix_sync(bf[j], sB + (wn + j * 16) * SROW + ks * 16, SROW);
#pragma unroll
            for (int i = 0; i < 2; i++)
#pragma unroll
                for (int j = 0; j < 3; j++)
                    wmma::mma_sync(acc[i][j], af[i], bf[j], acc[i][j]);
        }
        buf = (buf == 2) ? 0 : buf + 1;
    }

    __syncthreads();
    float* Cs = (float*)dyn_smem;       // [128][100]
#pragma unroll
    for (int i = 0; i < 2; i++)
#pragma unroll
        for (int j = 0; j < 3; j++)
            wmma::store_matrix_sync(&Cs[(wm + i * 16) * 100 + wn + j * 16], acc[i][j],
                                    100, wmma::mem_row_major);
    __syncthreads();

#pragma unroll
    for (int t = 0; t < 12; t++) {
        int q = tid + t * 256;          // 128 x 24 quads
        int row = q / 24;
        int col = (q % 24) * 4;
        float v0 = Cs[row * 100 + col + 0] + sbias[col + 0];
        float v1 = Cs[row * 100 + col + 1] + sbias[col + 1];
        float v2 = Cs[row * 100 + col + 2] + sbias[col + 2];
        float v3 = Cs[row * 100 + col + 3] + sbias[col + 3];
        int cg = n0 + col;
        int m = m0 + row;
        *(uint2*)(OutH + (size_t)m * LKB + cg) = pack4h(v0, v1, v2, v3);
    }
}

// ---------------- mean pool (fp16 in) -> g_mean fp32 ---------------------------
__global__ void mean_pool() {
    int idx = blockIdx.x * blockDim.x + threadIdx.x;
    if (idx >= C_OUT * LDF) return;
    int c = idx / LDF, f = idx % LDF;
    float s = 0.f;
    for (int n = 0; n < N_NODES; n++)
        s += __half2float(g_hh1[((size_t)n * C_OUT + c) * LKB + f]);
    g_mean[idx] = s * (1.f / N_NODES);
}

__device__ __forceinline__ float gelu_exact(float x) {
    return 0.5f * x * (1.f + erff(x * 0.70710678118654752f));
}

// ---------------- fc1 + gelu ----------------------------------------------------
__global__ void fc1_kernel(const float* __restrict__ w, const float* __restrict__ b) {
    __shared__ float row[F_DIM];
    int c = blockIdx.x;
    int tid = threadIdx.x;
    for (int f = tid; f < F_DIM; f += blockDim.x) row[f] = g_mean[c * LDF + f];
    __syncthreads();
    int warp = tid >> 5, lane = tid & 31;
    for (int g = warp; g < 128; g += blockDim.x / 32) {
        const float* wr = w + (size_t)g * F_DIM;
        float acc = 0.f;
        for (int f = lane; f < F_DIM; f += 32) acc = fmaf(row[f], wr[f], acc);
#pragma unroll
        for (int o = 16; o; o >>= 1) acc += __shfl_xor_sync(0xffffffffu, acc, o);
        if (lane == 0) g_fc1[c * 128 + g] = gelu_exact(acc + b[g]);
    }
}

// ---------------- fc2 + gelu + fc3 + softmax ------------------------------------
__global__ void head_kernel(const float* __restrict__ f2w, const float* __restrict__ f2b,
                            const float* __restrict__ f3w, const float* __restrict__ f3b,
                            float* __restrict__ out) {
    __shared__ float r1[128];
    __shared__ float r2[32];
    __shared__ float r3[4];
    int c = blockIdx.x;
    int tid = threadIdx.x;
    for (int i = tid; i < 128; i += 32) r1[i] = g_fc1[c * 128 + i];
    __syncthreads();
    {
        float acc = f2b[tid];
        const float* wr = f2w + (size_t)tid * 128;
        for (int f = 0; f < 128; f++) acc = fmaf(r1[f], wr[f], acc);
        r2[tid] = gelu_exact(acc);
    }
    __syncthreads();
    if (tid < 4) {
        float a = f3b[tid];
        const float* wr = f3w + (size_t)tid * 32;
        for (int f = 0; f < 32; f++) a = fmaf(r2[f], wr[f], a);
        r3[tid] = a;
    }
    __syncthreads();
    if (tid == 0) {
        float mx = fmaxf(fmaxf(r3[0], r3[1]), fmaxf(r3[2], r3[3]));
        float e0 = expf(r3[0] - mx), e1 = expf(r3[1] - mx);
        float e2 = expf(r3[2] - mx), e3 = expf(r3[3] - mx);
        float inv = 1.f / (e0 + e1 + e2 + e3);
        out[c * 4 + 0] = e0 * inv;
        out[c * 4 + 1] = e1 * inv;
        out[c * 4 + 2] = e2 * inv;
        out[c * 4 + 3] = e3 * inv;
    }
}

// ---------------- launch --------------------------------------------------------
extern "C" void kernel_launch(void* const* d_in, const int* in_sizes, int n_in,
                              void* d_out, int out_size) {
    const float* x      = (const float*)d_in[0];
    const int*   ei     = (const int*)d_in[1];
    const float* conv_w = (const float*)d_in[2];
    const float* conv_b = (const float*)d_in[3];
    const float* wl     = (const float*)d_in[4];
    const float* wr     = (const float*)d_in[5];
    const float* sb     = (const float*)d_in[6];
    const float* f1w    = (const float*)d_in[7];
    const float* f1b    = (const float*)d_in[8];
    const float* f2w    = (const float*)d_in[9];
    const float* f2b    = (const float*)d_in[10];
    const float* f3w    = (const float*)d_in[11];
    const float* f3b    = (const float*)d_in[12];
    float* out = (float*)d_out;

    cudaFuncSetAttribute(sage_gemm, cudaFuncAttributeMaxDynamicSharedMemorySize, GEMM_SMEM);

    build_csr<<<1, 128>>>(ei);
    cw_sage<<<(NPAD * (LKB / 4) + 255) / 256, 256>>>(wl, wr);
    cw_conv<<<(C_OUT * CK + 255) / 256, 256>>>(conv_w);
    conv_gemm<<<dim3(N_NODES * 6, 4), 256, CGEMM_SMEM>>>(x, conv_b);

    // 3 SAGE layers (fp16 ping-pong hh0 <-> hh1); layer 2 ends in hh1.
    for (int l = 0; l < 3; l++) {
        int src = l & 1;
        sage_agg<<<M_ROWS, 128>>>(src);
        sage_gemm<<<dim3(M_TILES, N_TILES), 256, GEMM_SMEM>>>(src, sb);
    }

    mean_pool<<<(C_OUT * LDF + 255) / 256, 256>>>();
    fc1_kernel<<<256, 128>>>(f1w, f1b);
    head_kernel<<<256, 32>>>(f2w, f2b, f3w, f3b, out);
}